// round 12
// baseline (speedup 1.0000x reference)
#include <cuda_runtime.h>
#include <cuda_fp16.h>
#include <cuda_bf16.h>
#include <math.h>
#include <stdint.h>

// ---------------- problem constants ----------------
#define D_MODEL 2048
#define NHEADS  16
#define HD      128
#define BATCH   2
#define SEQ     2048
#define MROWS   (BATCH*SEQ)   // 4096
#define BHS     (BATCH*NHEADS*SEQ)   // 65536

// fp32 scratch: Qlin,Klin,Vlin,AO
__device__ float g_scratch[4ULL * MROWS * D_MODEL];
// fp16 GEMM operands: Xhi,Xlo,AOhi,AOlo [4096x2048]; 4x (Whi,Wlo) [2048x2048]
__device__ __half g_half[4ULL * MROWS * D_MODEL + 8ULL * D_MODEL * D_MODEL];
// bf16 attention operands: Qhi,Qlo,Khi,Klo,Vhi,Vlo each [B,H,S,HD]
__device__ __nv_bfloat16 g_attn[6ULL * BHS * HD];

// ---------------- PTX helpers (portable: sm_75/80-era only) ----------------
__device__ __forceinline__ uint32_t smem_u32(const void* p) {
    uint32_t r;
    asm("{ .reg .u64 t; cvta.to.shared.u64 t, %1; cvt.u32.u64 %0, t; }"
        : "=r"(r) : "l"(p));
    return r;
}

__device__ __forceinline__ void cp16(uint32_t dst, const void* src) {
    asm volatile("cp.async.cg.shared.global [%0], [%1], 16;"
                 :: "r"(dst), "l"(src));
}

__device__ __forceinline__ void ldsm_x4(uint32_t* r, uint32_t addr) {
    asm volatile("ldmatrix.sync.aligned.m8n8.x4.shared.b16 {%0,%1,%2,%3}, [%4];"
                 : "=r"(r[0]), "=r"(r[1]), "=r"(r[2]), "=r"(r[3]) : "r"(addr));
}

__device__ __forceinline__ void ldsm_x4_t(uint32_t* r, uint32_t addr) {
    asm volatile("ldmatrix.sync.aligned.m8n8.x4.trans.shared.b16 {%0,%1,%2,%3}, [%4];"
                 : "=r"(r[0]), "=r"(r[1]), "=r"(r[2]), "=r"(r[3]) : "r"(addr));
}

__device__ __forceinline__ void mma_f16(float* d, const uint32_t* a, const uint32_t* b) {
    asm volatile(
        "mma.sync.aligned.m16n8k16.row.col.f32.f16.f16.f32 "
        "{%0,%1,%2,%3}, {%4,%5,%6,%7}, {%8,%9}, {%0,%1,%2,%3};"
        : "+f"(d[0]), "+f"(d[1]), "+f"(d[2]), "+f"(d[3])
        : "r"(a[0]), "r"(a[1]), "r"(a[2]), "r"(a[3]), "r"(b[0]), "r"(b[1]));
}

__device__ __forceinline__ void mma_bf16(float* d, const uint32_t* a, const uint32_t* b) {
    asm volatile(
        "mma.sync.aligned.m16n8k16.row.col.f32.bf16.bf16.f32 "
        "{%0,%1,%2,%3}, {%4,%5,%6,%7}, {%8,%9}, {%0,%1,%2,%3};"
        : "+f"(d[0]), "+f"(d[1]), "+f"(d[2]), "+f"(d[3])
        : "r"(a[0]), "r"(a[1]), "r"(a[2]), "r"(a[3]), "r"(b[0]), "r"(b[1]));
}

__device__ __forceinline__ void pack_hilo_bf(float a, float b, uint32_t& hi, uint32_t& lo) {
    __nv_bfloat162 th, tl;
    th.x = __float2bfloat16(a);
    th.y = __float2bfloat16(b);
    tl.x = __float2bfloat16(a - __bfloat162float(th.x));
    tl.y = __float2bfloat16(b - __bfloat162float(th.y));
    hi = *(uint32_t*)&th;
    lo = *(uint32_t*)&tl;
}

// ---------------- split fp32 -> fp16 hi + scaled lo ----------------
__global__ __launch_bounds__(256) void split2_kernel(
    const float* __restrict__ in, __half* __restrict__ hiO,
    __half* __restrict__ loO, int n)
{
    int idx = blockIdx.x * 256 + threadIdx.x;
    if (idx >= n) return;
    float v = in[idx];
    __half hi = __float2half(v);
    hiO[idx] = hi;
    loO[idx] = __float2half((v - __half2float(hi)) * 2048.0f);
}

// ---------------- fp16 dual-accumulator GEMM: C = A @ B^T + bias ----------------
// acc1 = Ahi Bhi^T ; acc2 = Alo_s Bhi^T + Ahi Blo_s^T ; C = acc1 + acc2/2048 + bias
#define BM 128
#define BN 128
#define BK 32
#define NSTAGE 3
#define NT (D_MODEL / BK)            // 64
#define ROWB 80
#define T_BYTES (BM * ROWB)          // 10240 per tile
#define STAGE_BYTES (4 * T_BYTES)    // 40960 (Ahi,Alo,Bhi,Blo)
#define GEMM_SMEM (NSTAGE * STAGE_BYTES)  // 122880

__global__ __launch_bounds__(256) void gemm_dual_kernel(
    const __half* __restrict__ Ahi, const __half* __restrict__ Alo,
    const __half* __restrict__ Bhi, const __half* __restrict__ Blo,
    const float* __restrict__ bias, float* __restrict__ C, int N)
{
    extern __shared__ __align__(128) char smraw[];
    const uint32_t smb = smem_u32(smraw);
    const int tid  = threadIdx.x;
    const int lane = tid & 31;
    const int wid  = tid >> 5;
    const int wm   = (wid >> 2) * 64;
    const int wn   = (wid & 3) * 32;
    const int rowBase = blockIdx.y * BM;
    const int colBase = blockIdx.x * BN;

    const char* g[4];
    g[0] = (const char*)Ahi + (size_t)rowBase * (D_MODEL * 2);
    g[1] = (const char*)Alo + (size_t)rowBase * (D_MODEL * 2);
    g[2] = (const char*)Bhi + (size_t)colBase * (D_MODEL * 2);
    g[3] = (const char*)Blo + (size_t)colBase * (D_MODEL * 2);

    float acc1[4][4][4], acc2[4][4][4];
    #pragma unroll
    for (int mi = 0; mi < 4; mi++)
        #pragma unroll
        for (int ni = 0; ni < 4; ni++)
            #pragma unroll
            for (int u = 0; u < 4; u++) { acc1[mi][ni][u] = 0.f; acc2[mi][ni][u] = 0.f; }

    // loader: 2048 chunks/stage, 256 threads x 8
    const int lr = (tid >> 1) & 127;        // row 0..127
    const int lc = (tid & 1) * 32;          // byte col 0/32 (2 chunks of 32B... use 16B x2)

    auto load_stage = [&](int kt) {
        if (kt < NT) {
            uint32_t base = smb + (kt % NSTAGE) * STAGE_BYTES;
            const size_t gk = (size_t)kt * 64;
            #pragma unroll
            for (int t4 = 0; t4 < 4; t4++) {
                const char* src = g[t4] + (size_t)lr * (D_MODEL * 2) + gk + lc;
                uint32_t dst = base + t4 * T_BYTES + lr * ROWB + lc;
                cp16(dst, src);
                cp16(dst + 16, src + 16);
            }
        }
        asm volatile("cp.async.commit_group;" ::: "memory");
    };

    load_stage(0);
    load_stage(1);

    const int a_row  = lane & 15;
    const int a_half = (lane >> 4) * 16;
    const int b_row  = ((lane >> 4) << 3) + (lane & 7);
    const int b_half = ((lane >> 3) & 1) * 16;

    for (int kt = 0; kt < NT; kt++) {
        asm volatile("cp.async.wait_group %0;" :: "n"(NSTAGE - 2) : "memory");
        __syncthreads();
        load_stage(kt + NSTAGE - 1);

        uint32_t st = smb + (kt % NSTAGE) * STAGE_BYTES;
        uint32_t AhiS = st, AloS = st + T_BYTES;
        uint32_t BhiS = st + 2 * T_BYTES, BloS = st + 3 * T_BYTES;

        #pragma unroll
        for (int j = 0; j < 2; j++) {
            uint32_t ah[4][4], al[4][4];
            #pragma unroll
            for (int mi = 0; mi < 4; mi++) {
                uint32_t off = (wm + mi * 16 + a_row) * ROWB + j * 32 + a_half;
                ldsm_x4(ah[mi], AhiS + off);
                ldsm_x4(al[mi], AloS + off);
            }
            uint32_t bh[2][4], bl[2][4];
            #pragma unroll
            for (int nb = 0; nb < 2; nb++) {
                uint32_t off = (wn + nb * 16 + b_row) * ROWB + j * 32 + b_half;
                ldsm_x4(bh[nb], BhiS + off);
                ldsm_x4(bl[nb], BloS + off);
            }
            #pragma unroll
            for (int mi = 0; mi < 4; mi++)
                #pragma unroll
                for (int ni = 0; ni < 4; ni++) {
                    const uint32_t* Bh = &bh[ni >> 1][(ni & 1) * 2];
                    const uint32_t* Bl = &bl[ni >> 1][(ni & 1) * 2];
                    mma_f16(acc1[mi][ni], ah[mi], Bh);
                    mma_f16(acc2[mi][ni], al[mi], Bh);
                    mma_f16(acc2[mi][ni], ah[mi], Bl);
                }
        }
        __syncthreads();
    }

    const float INV = 1.0f / 2048.0f;
    #pragma unroll
    for (int mi = 0; mi < 4; mi++) {
        int r0 = rowBase + wm + mi * 16 + (lane >> 2);
        #pragma unroll
        for (int ni = 0; ni < 4; ni++) {
            int cn = colBase + wn + ni * 8 + (lane & 3) * 2;
            float2 bv = *(const float2*)(bias + cn);
            float2 o0, o1;
            o0.x = fmaf(acc2[mi][ni][0], INV, acc1[mi][ni][0]) + bv.x;
            o0.y = fmaf(acc2[mi][ni][1], INV, acc1[mi][ni][1]) + bv.y;
            o1.x = fmaf(acc2[mi][ni][2], INV, acc1[mi][ni][2]) + bv.x;
            o1.y = fmaf(acc2[mi][ni][3], INV, acc1[mi][ni][3]) + bv.y;
            *(float2*)(C + (size_t)r0 * N + cn) = o0;
            *(float2*)(C + (size_t)(r0 + 8) * N + cn) = o1;
        }
    }
}

// ---------------- RoPE (reference-exact) -> bf16 hi/lo Q,K,V [B,H,S,HD] ----------------
__global__ __launch_bounds__(256) void rope_split_kernel(
    const float* __restrict__ Qlin, const float* __restrict__ Klin,
    const float* __restrict__ Vlin,
    __nv_bfloat16* __restrict__ Qhi, __nv_bfloat16* __restrict__ Qlo,
    __nv_bfloat16* __restrict__ Khi, __nv_bfloat16* __restrict__ Klo,
    __nv_bfloat16* __restrict__ Vhi, __nv_bfloat16* __restrict__ Vlo)
{
    int idx = blockIdx.x * blockDim.x + threadIdx.x;   // [B,H,S,HD] flat
    int d = idx & (HD - 1);
    int s = (idx >> 7) & (SEQ - 1);
    int h = (idx >> 18) & (NHEADS - 1);
    int b = idx >> 22;

    size_t src = ((size_t)(b * SEQ + s)) * D_MODEL + h * HD + d;
    int j = d & 63;
    float invf = expf(-(float)j * (9.210340371976184f / 64.0f));
    float ang  = (float)s * invf;
    float e    = (d < 64) ? sinf(ang) : cosf(ang);     // emb (reference quirk)
    float ce   = cosf(e);
    float se   = sinf(e);

    size_t srcP = (d < 64) ? src + 64 : src - 64;
    float sgn   = (d < 64) ? -1.0f : 1.0f;

    float q = Qlin[src], qp = Qlin[srcP];
    float k = Klin[src], kp = Klin[srcP];
    float qr = fmaf(q, ce, sgn * qp * se);
    float kr = fmaf(k, ce, sgn * kp * se);
    float v  = Vlin[src];

    __nv_bfloat16 qh = __float2bfloat16(qr);
    __nv_bfloat16 kh = __float2bfloat16(kr);
    __nv_bfloat16 vh = __float2bfloat16(v);
    Qhi[idx] = qh; Qlo[idx] = __float2bfloat16(qr - __bfloat162float(qh));
    Khi[idx] = kh; Klo[idx] = __float2bfloat16(kr - __bfloat162float(kh));
    Vhi[idx] = vh; Vlo[idx] = __float2bfloat16(v  - __bfloat162float(vh));
}

// ---------------- tensor-core flash attention (bf16 3-term, R9-proven) ----------------
#define ATQ 128
#define ATK 64
#define AROWB 272
#define Q_ARR (ATQ * AROWB)
#define KV_ARR (ATK * AROWB)
#define KV_STAGE (4 * KV_ARR)
#define KV_OFF (2 * Q_ARR)
#define ATTN_SMEM (KV_OFF + 2 * KV_STAGE)  // 208896
#define NKT (SEQ / ATK)

__global__ __launch_bounds__(256) void attn_mma_kernel(
    const __nv_bfloat16* __restrict__ Qhi, const __nv_bfloat16* __restrict__ Qlo,
    const __nv_bfloat16* __restrict__ Khi, const __nv_bfloat16* __restrict__ Klo,
    const __nv_bfloat16* __restrict__ Vhi, const __nv_bfloat16* __restrict__ Vlo,
    float* __restrict__ O)
{
    extern __shared__ __align__(128) char smraw[];
    const uint32_t smb = smem_u32(smraw);
    const int tid  = threadIdx.x;
    const int lane = tid & 31;
    const int wid  = tid >> 5;
    const int qBase = blockIdx.x * ATQ;
    const int h = blockIdx.y;
    const int b = blockIdx.z;
    const size_t bh = (size_t)b * NHEADS + h;

    const char* Qhg = (const char*)Qhi + (bh * SEQ + qBase) * (HD * 2);
    const char* Qlg = (const char*)Qlo + (bh * SEQ + qBase) * (HD * 2);
    const char* Khg = (const char*)Khi + bh * SEQ * (HD * 2);
    const char* Klg = (const char*)Klo + bh * SEQ * (HD * 2);
    const char* Vhg = (const char*)Vhi + bh * SEQ * (HD * 2);
    const char* Vlg = (const char*)Vlo + bh * SEQ * (HD * 2);

    #pragma unroll
    for (int i = 0; i < 16; i++) {
        int idx = tid + i * 256;
        int arr = idx >> 11;
        int r   = (idx >> 4) & 127;
        int c   = (idx & 15) * 16;
        const char* sp = arr ? Qlg : Qhg;
        cp16(smb + arr * Q_ARR + r * AROWB + c, sp + (size_t)r * 256 + c);
    }
    asm volatile("cp.async.commit_group;" ::: "memory");

    auto loadKV = [&](int kt) {
        int s = kt & 1;
        #pragma unroll
        for (int i = 0; i < 16; i++) {
            int idx = tid + i * 256;
            int arr = idx >> 10;
            int r   = (idx >> 4) & 63;
            int c   = (idx & 15) * 16;
            const char* sp = (arr == 0) ? Khg : (arr == 1) ? Klg
                           : (arr == 2) ? Vhg : Vlg;
            cp16(smb + KV_OFF + s * KV_STAGE + arr * KV_ARR + r * AROWB + c,
                 sp + (size_t)(kt * ATK + r) * 256 + c);
        }
        asm volatile("cp.async.commit_group;" ::: "memory");
    };

    loadKV(0);

    float oAcc[16][4];
    #pragma unroll
    for (int t2 = 0; t2 < 16; t2++)
        #pragma unroll
        for (int u = 0; u < 4; u++) oAcc[t2][u] = 0.f;
    float mA = -INFINITY, mB = -INFINITY, lA = 0.f, lB = 0.f;

    const int m0 = wid * 16;
    const int a_row  = lane & 15;
    const int a_halfB = (lane >> 4) * 16;
    const int b_row  = ((lane >> 4) << 3) + (lane & 7);
    const int b_halfB = ((lane >> 3) & 1) * 16;
    const float SCALE = 0.08838834764831845f;

    for (int kt = 0; kt < NKT; kt++) {
        if (kt + 1 < NKT) {
            loadKV(kt + 1);
            asm volatile("cp.async.wait_group 1;" ::: "memory");
        } else {
            asm volatile("cp.async.wait_group 0;" ::: "memory");
        }
        __syncthreads();

        const uint32_t kb   = smb + KV_OFF + (kt & 1) * KV_STAGE;
        const uint32_t KhiS = kb;
        const uint32_t KloS = kb + KV_ARR;
        const uint32_t VhiS = kb + 2 * KV_ARR;
        const uint32_t VloS = kb + 3 * KV_ARR;

        float sAcc[8][4];
        #pragma unroll
        for (int ni = 0; ni < 8; ni++)
            #pragma unroll
            for (int u = 0; u < 4; u++) sAcc[ni][u] = 0.f;

        #pragma unroll
        for (int j = 0; j < 8; j++) {
            uint32_t ah[4], al[4];
            uint32_t aoff = (m0 + a_row) * AROWB + j * 32 + a_halfB;
            ldsm_x4(ah, smb + aoff);
            ldsm_x4(al, smb + Q_ARR + aoff);
            uint32_t bh_[4][4], bl_[4][4];
            #pragma unroll
            for (int nb = 0; nb < 4; nb++) {
                uint32_t boff = (nb * 16 + b_row) * AROWB + j * 32 + b_halfB;
                ldsm_x4(bh_[nb], KhiS + boff);
                ldsm_x4(bl_[nb], KloS + boff);
            }
            #pragma unroll
            for (int ni = 0; ni < 8; ni++) {
                const uint32_t* Bh = &bh_[ni >> 1][(ni & 1) * 2];
                const uint32_t* Bl = &bl_[ni >> 1][(ni & 1) * 2];
                mma_bf16(sAcc[ni], ah, Bh);
                mma_bf16(sAcc[ni], al, Bh);
                mma_bf16(sAcc[ni], ah, Bl);
            }
        }

        float mxA = -INFINITY, mxB = -INFINITY;
        #pragma unroll
        for (int ni = 0; ni < 8; ni++) {
            #pragma unroll
            for (int u = 0; u < 4; u++) sAcc[ni][u] *= SCALE;
            mxA = fmaxf(mxA, fmaxf(sAcc[ni][0], sAcc[ni][1]));
            mxB = fmaxf(mxB, fmaxf(sAcc[ni][2], sAcc[ni][3]));
        }
        mxA = fmaxf(mxA, __shfl_xor_sync(0xffffffff, mxA, 1));
        mxA = fmaxf(mxA, __shfl_xor_sync(0xffffffff, mxA, 2));
        mxB = fmaxf(mxB, __shfl_xor_sync(0xffffffff, mxB, 1));
        mxB = fmaxf(mxB, __shfl_xor_sync(0xffffffff, mxB, 2));

        float mAn = fmaxf(mA, mxA), mBn = fmaxf(mB, mxB);
        float cA = __expf(mA - mAn), cB = __expf(mB - mBn);
        mA = mAn; mB = mBn;

        float sumA = 0.f, sumB = 0.f;
        #pragma unroll
        for (int ni = 0; ni < 8; ni++) {
            sAcc[ni][0] = __expf(sAcc[ni][0] - mA);
            sAcc[ni][1] = __expf(sAcc[ni][1] - mA);
            sAcc[ni][2] = __expf(sAcc[ni][2] - mB);
            sAcc[ni][3] = __expf(sAcc[ni][3] - mB);
            sumA += sAcc[ni][0] + sAcc[ni][1];
            sumB += sAcc[ni][2] + sAcc[ni][3];
        }
        sumA += __shfl_xor_sync(0xffffffff, sumA, 1);
        sumA += __shfl_xor_sync(0xffffffff, sumA, 2);
        sumB += __shfl_xor_sync(0xffffffff, sumB, 1);
        sumB += __shfl_xor_sync(0xffffffff, sumB, 2);
        lA = lA * cA + sumA;
        lB = lB * cB + sumB;

        #pragma unroll
        for (int t2 = 0; t2 < 16; t2++) {
            oAcc[t2][0] *= cA; oAcc[t2][1] *= cA;
            oAcc[t2][2] *= cB; oAcc[t2][3] *= cB;
        }

        uint32_t phi[4][4], plo[4][4];
        #pragma unroll
        for (int j2 = 0; j2 < 4; j2++) {
            pack_hilo_bf(sAcc[2*j2][0],   sAcc[2*j2][1],   phi[j2][0], plo[j2][0]);
            pack_hilo_bf(sAcc[2*j2][2],   sAcc[2*j2][3],   phi[j2][1], plo[j2][1]);
            pack_hilo_bf(sAcc[2*j2+1][0], sAcc[2*j2+1][1], phi[j2][2], plo[j2][2]);
            pack_hilo_bf(sAcc[2*j2+1][2], sAcc[2*j2+1][3], phi[j2][3], plo[j2][3]);
        }

        #pragma unroll
        for (int j2 = 0; j2 < 4; j2++) {
            int key0 = j2 * 16;
            #pragma unroll
            for (int nb = 0; nb < 8; nb++) {
                uint32_t vh[4], vl[4];
                uint32_t voff = (key0 + (lane & 15)) * AROWB
                              + (nb * 16 + ((lane >> 4) << 3)) * 2;
                ldsm_x4_t(vh, VhiS + voff);
                ldsm_x4_t(vl, VloS + voff);
                mma_bf16(oAcc[2*nb],   phi[j2], vh);
                mma_bf16(oAcc[2*nb],   plo[j2], vh);
                mma_bf16(oAcc[2*nb],   phi[j2], vl);
                mma_bf16(oAcc[2*nb+1], phi[j2], vh + 2);
                mma_bf16(oAcc[2*nb+1], plo[j2], vh + 2);
                mma_bf16(oAcc[2*nb+1], phi[j2], vl + 2);
            }
        }
        __syncthreads();
    }

    float invA = 1.0f / lA, invB = 1.0f / lB;
    int rA = qBase + m0 + (lane >> 2);
    int rB = rA + 8;
    float* outA = O + ((size_t)(b * SEQ + rA)) * D_MODEL + h * HD;
    float* outB = O + ((size_t)(b * SEQ + rB)) * D_MODEL + h * HD;
    #pragma unroll
    for (int t2 = 0; t2 < 16; t2++) {
        int cn = t2 * 8 + (lane & 3) * 2;
        float2 oa, ob;
        oa.x = oAcc[t2][0] * invA; oa.y = oAcc[t2][1] * invA;
        ob.x = oAcc[t2][2] * invB; ob.y = oAcc[t2][3] * invB;
        *(float2*)(outA + cn) = oa;
        *(float2*)(outB + cn) = ob;
    }
}

// ---------------- launch ----------------
extern "C" void kernel_launch(void* const* d_in, const int* in_sizes, int n_in,
                              void* d_out, int out_size)
{
    const float* x  = (const float*)d_in[0];
    const float* Wq = (const float*)d_in[1];
    const float* bq = (const float*)d_in[2];
    const float* Wk = (const float*)d_in[3];
    const float* bk = (const float*)d_in[4];
    const float* Wv = (const float*)d_in[5];
    const float* bv = (const float*)d_in[6];
    const float* Wo = (const float*)d_in[7];
    const float* bo = (const float*)d_in[8];
    float* out = (float*)d_out;

    float* scratch = nullptr;
    cudaGetSymbolAddress((void**)&scratch, g_scratch);
    const size_t NMe = (size_t)MROWS * D_MODEL;
    float* Qlin = scratch + 0 * NMe;
    float* Klin = scratch + 1 * NMe;
    float* Vlin = scratch + 2 * NMe;
    float* AO   = scratch + 3 * NMe;

    __half* hp = nullptr;
    cudaGetSymbolAddress((void**)&hp, g_half);
    const size_t WE = (size_t)D_MODEL * D_MODEL;   // 4M
    __half* Xhi  = hp + 0 * WE;   // X is 2 weight-sizes (4096x2048)
    __half* Xlo  = hp + 2 * WE;
    __half* AOhi = hp + 4 * WE;
    __half* AOlo = hp + 6 * WE;
    __half* WqHi = hp + 8 * WE;
    __half* WqLo = hp + 9 * WE;
    __half* WkHi = hp + 10 * WE;
    __half* WkLo = hp + 11 * WE;
    __half* WvHi = hp + 12 * WE;
    __half* WvLo = hp + 13 * WE;
    __half* WoHi = hp + 14 * WE;
    __half* WoLo = hp + 15 * WE;

    __nv_bfloat16* ap = nullptr;
    cudaGetSymbolAddress((void**)&ap, g_attn);
    const size_t AH = (size_t)BHS * HD;
    __nv_bfloat16* Qhi = ap + 0 * AH;
    __nv_bfloat16* Qlo = ap + 1 * AH;
    __nv_bfloat16* Khi = ap + 2 * AH;
    __nv_bfloat16* Klo = ap + 3 * AH;
    __nv_bfloat16* Vhi = ap + 4 * AH;
    __nv_bfloat16* Vlo = ap + 5 * AH;

    cudaFuncSetAttribute(gemm_dual_kernel, cudaFuncAttributeMaxDynamicSharedMemorySize,
                         GEMM_SMEM);
    cudaFuncSetAttribute(attn_mma_kernel, cudaFuncAttributeMaxDynamicSharedMemorySize,
                         ATTN_SMEM);

    // splits
    int nX = MROWS * D_MODEL, nW = D_MODEL * D_MODEL;
    split2_kernel<<<nX / 256, 256>>>(x,  Xhi, Xlo, nX);
    split2_kernel<<<nW / 256, 256>>>(Wq, WqHi, WqLo, nW);
    split2_kernel<<<nW / 256, 256>>>(Wk, WkHi, WkLo, nW);
    split2_kernel<<<nW / 256, 256>>>(Wv, WvHi, WvLo, nW);
    split2_kernel<<<nW / 256, 256>>>(Wo, WoHi, WoLo, nW);

    dim3 ggrid(D_MODEL / BN, MROWS / BM);   // (16, 32)
    gemm_dual_kernel<<<ggrid, 256, GEMM_SMEM>>>(Xhi, Xlo, WqHi, WqLo, bq, Qlin, D_MODEL);
    gemm_dual_kernel<<<ggrid, 256, GEMM_SMEM>>>(Xhi, Xlo, WkHi, WkLo, bk, Klin, D_MODEL);
    gemm_dual_kernel<<<ggrid, 256, GEMM_SMEM>>>(Xhi, Xlo, WvHi, WvLo, bv, Vlin, D_MODEL);

    int total = BATCH * NHEADS * SEQ * HD;
    rope_split_kernel<<<total / 256, 256>>>(Qlin, Klin, Vlin,
                                            Qhi, Qlo, Khi, Klo, Vhi, Vlo);

    attn_mma_kernel<<<dim3(SEQ / ATQ, NHEADS, BATCH), 256, ATTN_SMEM>>>(
        Qhi, Qlo, Khi, Klo, Vhi, Vlo, AO);

    split2_kernel<<<nX / 256, 256>>>(AO, AOhi, AOlo, nX);
    gemm_dual_kernel<<<ggrid, 256, GEMM_SMEM>>>(AOhi, AOlo, WoHi, WoLo, bo, out, D_MODEL);
}

// round 14
// speedup vs baseline: 1.1000x; 1.1000x over previous
#include <cuda_runtime.h>
#include <cuda_bf16.h>
#include <math.h>
#include <stdint.h>

// ---------------- problem constants ----------------
#define D_MODEL 2048
#define NHEADS  16
#define HD      128
#define BATCH   2
#define SEQ     2048
#define MROWS   (BATCH*SEQ)   // 4096
#define KTOT    (3*D_MODEL)   // 6144 (3-term bf16 split along K)
#define BHS     (BATCH*NHEADS*SEQ)   // 65536

// fp32 scratch: Qlin,Klin,Vlin,AO
__device__ float g_scratch[4ULL * MROWS * D_MODEL];
// bf16 scratch for GEMMs: Xhat, AOhat, 4x What
__device__ __nv_bfloat16 g_bf16[2ULL * MROWS * KTOT + 4ULL * D_MODEL * KTOT];
// bf16 scratch for attention: Qhi,Qlo,Khi,Klo,Vhi,Vlo each [B,H,S,HD]
__device__ __nv_bfloat16 g_attn[6ULL * BHS * HD];

// ---------------- PTX helpers (portable: sm_75/80-era only) ----------------
__device__ __forceinline__ uint32_t smem_u32(const void* p) {
    uint32_t r;
    asm("{ .reg .u64 t; cvta.to.shared.u64 t, %1; cvt.u32.u64 %0, t; }"
        : "=r"(r) : "l"(p));
    return r;
}

__device__ __forceinline__ void cp16(uint32_t dst, const void* src) {
    asm volatile("cp.async.cg.shared.global [%0], [%1], 16;"
                 :: "r"(dst), "l"(src));
}

__device__ __forceinline__ void ldsm_x4(uint32_t* r, uint32_t addr) {
    asm volatile("ldmatrix.sync.aligned.m8n8.x4.shared.b16 {%0,%1,%2,%3}, [%4];"
                 : "=r"(r[0]), "=r"(r[1]), "=r"(r[2]), "=r"(r[3]) : "r"(addr));
}

__device__ __forceinline__ void ldsm_x4_t(uint32_t* r, uint32_t addr) {
    asm volatile("ldmatrix.sync.aligned.m8n8.x4.trans.shared.b16 {%0,%1,%2,%3}, [%4];"
                 : "=r"(r[0]), "=r"(r[1]), "=r"(r[2]), "=r"(r[3]) : "r"(addr));
}

__device__ __forceinline__ void mma_bf16(float* d, const uint32_t* a, const uint32_t* b) {
    asm volatile(
        "mma.sync.aligned.m16n8k16.row.col.f32.bf16.bf16.f32 "
        "{%0,%1,%2,%3}, {%4,%5,%6,%7}, {%8,%9}, {%0,%1,%2,%3};"
        : "+f"(d[0]), "+f"(d[1]), "+f"(d[2]), "+f"(d[3])
        : "r"(a[0]), "r"(a[1]), "r"(a[2]), "r"(a[3]), "r"(b[0]), "r"(b[1]));
}

__device__ __forceinline__ void pack_hilo(float a, float b, uint32_t& hi, uint32_t& lo) {
    __nv_bfloat162 th, tl;
    th.x = __float2bfloat16(a);
    th.y = __float2bfloat16(b);
    tl.x = __float2bfloat16(a - __bfloat162float(th.x));
    tl.y = __float2bfloat16(b - __bfloat162float(th.y));
    hi = *(uint32_t*)&th;
    lo = *(uint32_t*)&tl;
}

// ---------------- split fp32 -> 3-term bf16 ----------------
// A-side (isW=0): [hi | lo | hi]    W-side (isW=1): [hi | hi | lo]
__global__ __launch_bounds__(256) void split_kernel(
    const float* __restrict__ in, __nv_bfloat16* __restrict__ out, int isW)
{
    int idx = blockIdx.x * 256 + threadIdx.x;
    int r = idx >> 11;
    int k = idx & 2047;
    float v = in[idx];
    __nv_bfloat16 hi = __float2bfloat16(v);
    __nv_bfloat16 lo = __float2bfloat16(v - __bfloat162float(hi));
    __nv_bfloat16* o = out + (size_t)r * KTOT;
    if (isW) { o[k] = hi; o[D_MODEL + k] = hi; o[2 * D_MODEL + k] = lo; }
    else     { o[k] = hi; o[D_MODEL + k] = lo; o[2 * D_MODEL + k] = hi; }
}

// ---------------- mma.sync bf16 GEMM (R9-proven, verbatim) ----------------
#define BM 128
#define BN 128
#define BK 32
#define NSTAGE 3
#define NT (KTOT / BK)               // 192
#define ROWB 80
#define A_BYTES (BM * ROWB)          // 10240
#define STAGE_BYTES (2 * BM * ROWB)  // 20480
#define GEMM_SMEM (NSTAGE * STAGE_BYTES)  // 61440

__global__ __launch_bounds__(256) void gemm_mma_kernel(
    const __nv_bfloat16* __restrict__ A, const __nv_bfloat16* __restrict__ B,
    const float* __restrict__ bias, float* __restrict__ C, int N)
{
    extern __shared__ __align__(128) char smraw[];
    const uint32_t smb = smem_u32(smraw);
    const int tid  = threadIdx.x;
    const int lane = tid & 31;
    const int wid  = tid >> 5;
    const int wm   = (wid >> 2) * 64;
    const int wn   = (wid & 3) * 32;
    const int rowBase = blockIdx.y * BM;
    const int colBase = blockIdx.x * BN;

    const char* Ag = (const char*)A + (size_t)rowBase * (KTOT * 2);
    const char* Bg = (const char*)B + (size_t)colBase * (KTOT * 2);

    float acc[4][4][4];
    #pragma unroll
    for (int mi = 0; mi < 4; mi++)
        #pragma unroll
        for (int ni = 0; ni < 4; ni++)
            #pragma unroll
            for (int u = 0; u < 4; u++) acc[mi][ni][u] = 0.f;

    const int lr0 = tid >> 2;
    const int lc  = (tid & 3) * 16;

    auto load_stage = [&](int kt) {
        if (kt < NT) {
            uint32_t base = smb + (kt % NSTAGE) * STAGE_BYTES;
            const size_t gk = (size_t)kt * 64;
            #pragma unroll
            for (int i = 0; i < 2; i++) {
                int r = lr0 + i * 64;
                cp16(base + r * ROWB + lc, Ag + (size_t)r * (KTOT * 2) + gk + lc);
            }
            #pragma unroll
            for (int i = 0; i < 2; i++) {
                int r = lr0 + i * 64;
                cp16(base + A_BYTES + r * ROWB + lc,
                     Bg + (size_t)r * (KTOT * 2) + gk + lc);
            }
        }
        asm volatile("cp.async.commit_group;" ::: "memory");
    };

    load_stage(0);
    load_stage(1);

    const int a_row  = lane & 15;
    const int a_half = (lane >> 4) * 16;
    const int b_row  = ((lane >> 4) << 3) + (lane & 7);
    const int b_half = ((lane >> 3) & 1) * 16;

    for (int kt = 0; kt < NT; kt++) {
        asm volatile("cp.async.wait_group %0;" :: "n"(NSTAGE - 2) : "memory");
        __syncthreads();
        load_stage(kt + NSTAGE - 1);

        uint32_t aBase = smb + (kt % NSTAGE) * STAGE_BYTES;
        uint32_t bBase = aBase + A_BYTES;

        #pragma unroll
        for (int j = 0; j < 2; j++) {
            uint32_t af[4][4];
            #pragma unroll
            for (int mi = 0; mi < 4; mi++)
                ldsm_x4(af[mi],
                        aBase + (wm + mi * 16 + a_row) * ROWB + j * 32 + a_half);
            uint32_t bf[2][4];
            #pragma unroll
            for (int nb = 0; nb < 2; nb++)
                ldsm_x4(bf[nb],
                        bBase + (wn + nb * 16 + b_row) * ROWB + j * 32 + b_half);
            #pragma unroll
            for (int mi = 0; mi < 4; mi++)
                #pragma unroll
                for (int ni = 0; ni < 4; ni++)
                    mma_bf16(acc[mi][ni], af[mi], &bf[ni >> 1][(ni & 1) * 2]);
        }
        __syncthreads();
    }

    #pragma unroll
    for (int mi = 0; mi < 4; mi++) {
        int r0 = rowBase + wm + mi * 16 + (lane >> 2);
        #pragma unroll
        for (int ni = 0; ni < 4; ni++) {
            int cn = colBase + wn + ni * 8 + (lane & 3) * 2;
            float2 bv = *(const float2*)(bias + cn);
            float2 o0, o1;
            o0.x = acc[mi][ni][0] + bv.x; o0.y = acc[mi][ni][1] + bv.y;
            o1.x = acc[mi][ni][2] + bv.x; o1.y = acc[mi][ni][3] + bv.y;
            *(float2*)(C + (size_t)r0 * N + cn) = o0;
            *(float2*)(C + (size_t)(r0 + 8) * N + cn) = o1;
        }
    }
}

// ---------------- RoPE (reference-exact) -> bf16 hi/lo Q,K,V [B,H,S,HD] ----------------
__global__ __launch_bounds__(256) void rope_split_kernel(
    const float* __restrict__ Qlin, const float* __restrict__ Klin,
    const float* __restrict__ Vlin,
    __nv_bfloat16* __restrict__ Qhi, __nv_bfloat16* __restrict__ Qlo,
    __nv_bfloat16* __restrict__ Khi, __nv_bfloat16* __restrict__ Klo,
    __nv_bfloat16* __restrict__ Vhi, __nv_bfloat16* __restrict__ Vlo)
{
    int idx = blockIdx.x * blockDim.x + threadIdx.x;   // [B,H,S,HD] flat
    int d = idx & (HD - 1);
    int s = (idx >> 7) & (SEQ - 1);
    int h = (idx >> 18) & (NHEADS - 1);
    int b = idx >> 22;

    size_t src = ((size_t)(b * SEQ + s)) * D_MODEL + h * HD + d;
    int j = d & 63;
    float invf = expf(-(float)j * (9.210340371976184f / 64.0f));
    float ang  = (float)s * invf;
    float e    = (d < 64) ? sinf(ang) : cosf(ang);     // emb (reference quirk)
    float ce   = cosf(e);
    float se   = sinf(e);

    size_t srcP = (d < 64) ? src + 64 : src - 64;
    float sgn   = (d < 64) ? -1.0f : 1.0f;

    float q = Qlin[src], qp = Qlin[srcP];
    float k = Klin[src], kp = Klin[srcP];
    float qr = fmaf(q, ce, sgn * qp * se);
    float kr = fmaf(k, ce, sgn * kp * se);
    float v  = Vlin[src];

    __nv_bfloat16 qh = __float2bfloat16(qr);
    __nv_bfloat16 kh = __float2bfloat16(kr);
    __nv_bfloat16 vh = __float2bfloat16(v);
    Qhi[idx] = qh; Qlo[idx] = __float2bfloat16(qr - __bfloat162float(qh));
    Khi[idx] = kh; Klo[idx] = __float2bfloat16(kr - __bfloat162float(kh));
    Vhi[idx] = vh; Vlo[idx] = __float2bfloat16(v  - __bfloat162float(vh));
}

// ---------------- tensor-core flash attention (bf16 3-term, 2 CTAs/SM) ----------------
// 4 warps x 16 q-rows = 64 q-rows/CTA; k-tiles of 32, double-buffered.
// smem 104448 B -> 2 CTAs/SM for cross-CTA latency hiding.
#define ATQ 64
#define ATK 32
#define ATHR 128
#define AROWB 272
#define Q_ARR (ATQ * AROWB)            // 17408
#define KV_ARR (ATK * AROWB)           // 8704
#define KV_STAGE (4 * KV_ARR)          // 34816 (Khi,Klo,Vhi,Vlo)
#define KV_OFF (2 * Q_ARR)             // 34816
#define ATTN_SMEM (KV_OFF + 2 * KV_STAGE)  // 104448
#define NKT (SEQ / ATK)                // 64

__global__ __launch_bounds__(ATHR, 2) void attn_mma_kernel(
    const __nv_bfloat16* __restrict__ Qhi, const __nv_bfloat16* __restrict__ Qlo,
    const __nv_bfloat16* __restrict__ Khi, const __nv_bfloat16* __restrict__ Klo,
    const __nv_bfloat16* __restrict__ Vhi, const __nv_bfloat16* __restrict__ Vlo,
    float* __restrict__ O)
{
    extern __shared__ __align__(128) char smraw[];
    const uint32_t smb = smem_u32(smraw);
    const int tid  = threadIdx.x;
    const int lane = tid & 31;
    const int wid  = tid >> 5;
    const int qBase = blockIdx.x * ATQ;
    const int h = blockIdx.y;
    const int b = blockIdx.z;
    const size_t bh = (size_t)b * NHEADS + h;

    const char* Qhg = (const char*)Qhi + (bh * SEQ + qBase) * (HD * 2);
    const char* Qlg = (const char*)Qlo + (bh * SEQ + qBase) * (HD * 2);
    const char* Khg = (const char*)Khi + bh * SEQ * (HD * 2);
    const char* Klg = (const char*)Klo + bh * SEQ * (HD * 2);
    const char* Vhg = (const char*)Vhi + bh * SEQ * (HD * 2);
    const char* Vlg = (const char*)Vlo + bh * SEQ * (HD * 2);

    // ---- load Q hi/lo (persistent smem): 2048 x 16B chunks ----
    #pragma unroll
    for (int i = 0; i < 16; i++) {
        int idx = tid + i * ATHR;
        int arr = idx >> 10;                 // 0:hi 1:lo
        int r   = (idx >> 4) & 63;
        int c   = (idx & 15) * 16;
        const char* sp = arr ? Qlg : Qhg;
        cp16(smb + arr * Q_ARR + r * AROWB + c, sp + (size_t)r * 256 + c);
    }
    asm volatile("cp.async.commit_group;" ::: "memory");

    auto loadKV = [&](int kt) {
        int s = kt & 1;
        #pragma unroll
        for (int i = 0; i < 16; i++) {
            int idx = tid + i * ATHR;        // 2048 chunks
            int arr = idx >> 9;              // 0..3
            int r   = (idx >> 4) & 31;
            int c   = (idx & 15) * 16;
            const char* sp = (arr == 0) ? Khg : (arr == 1) ? Klg
                           : (arr == 2) ? Vhg : Vlg;
            cp16(smb + KV_OFF + s * KV_STAGE + arr * KV_ARR + r * AROWB + c,
                 sp + (size_t)(kt * ATK + r) * 256 + c);
        }
        asm volatile("cp.async.commit_group;" ::: "memory");
    };

    loadKV(0);

    float oAcc[16][4];
    #pragma unroll
    for (int t2 = 0; t2 < 16; t2++)
        #pragma unroll
        for (int u = 0; u < 4; u++) oAcc[t2][u] = 0.f;
    float mA = -INFINITY, mB = -INFINITY, lA = 0.f, lB = 0.f;

    const int m0 = wid * 16;
    const int a_row  = lane & 15;
    const int a_halfB = (lane >> 4) * 16;
    const int b_row  = ((lane >> 4) << 3) + (lane & 7);
    const int b_halfB = ((lane >> 3) & 1) * 16;
    const float SCALE = 0.08838834764831845f;          // 1/sqrt(128)

    for (int kt = 0; kt < NKT; kt++) {
        if (kt + 1 < NKT) {
            loadKV(kt + 1);
            asm volatile("cp.async.wait_group 1;" ::: "memory");
        } else {
            asm volatile("cp.async.wait_group 0;" ::: "memory");
        }
        __syncthreads();

        const uint32_t kb   = smb + KV_OFF + (kt & 1) * KV_STAGE;
        const uint32_t KhiS = kb;
        const uint32_t KloS = kb + KV_ARR;
        const uint32_t VhiS = kb + 2 * KV_ARR;
        const uint32_t VloS = kb + 3 * KV_ARR;

        // ---- S = scale * (Qhi Khi^T + Qlo Khi^T + Qhi Klo^T), 16x32 per warp ----
        float sAcc[4][4];
        #pragma unroll
        for (int ni = 0; ni < 4; ni++)
            #pragma unroll
            for (int u = 0; u < 4; u++) sAcc[ni][u] = 0.f;

        #pragma unroll
        for (int j = 0; j < 8; j++) {
            uint32_t ah[4], al[4];
            uint32_t aoff = (m0 + a_row) * AROWB + j * 32 + a_halfB;
            ldsm_x4(ah, smb + aoff);
            ldsm_x4(al, smb + Q_ARR + aoff);
            uint32_t bh_[2][4], bl_[2][4];
            #pragma unroll
            for (int nb = 0; nb < 2; nb++) {
                uint32_t boff = (nb * 16 + b_row) * AROWB + j * 32 + b_halfB;
                ldsm_x4(bh_[nb], KhiS + boff);
                ldsm_x4(bl_[nb], KloS + boff);
            }
            #pragma unroll
            for (int ni = 0; ni < 4; ni++) {
                const uint32_t* Bh = &bh_[ni >> 1][(ni & 1) * 2];
                const uint32_t* Bl = &bl_[ni >> 1][(ni & 1) * 2];
                mma_bf16(sAcc[ni], ah, Bh);
                mma_bf16(sAcc[ni], al, Bh);
                mma_bf16(sAcc[ni], ah, Bl);
            }
        }

        // ---- online softmax (rows lane>>2 and +8, quad-local) ----
        float mxA = -INFINITY, mxB = -INFINITY;
        #pragma unroll
        for (int ni = 0; ni < 4; ni++) {
            #pragma unroll
            for (int u = 0; u < 4; u++) sAcc[ni][u] *= SCALE;
            mxA = fmaxf(mxA, fmaxf(sAcc[ni][0], sAcc[ni][1]));
            mxB = fmaxf(mxB, fmaxf(sAcc[ni][2], sAcc[ni][3]));
        }
        mxA = fmaxf(mxA, __shfl_xor_sync(0xffffffff, mxA, 1));
        mxA = fmaxf(mxA, __shfl_xor_sync(0xffffffff, mxA, 2));
        mxB = fmaxf(mxB, __shfl_xor_sync(0xffffffff, mxB, 1));
        mxB = fmaxf(mxB, __shfl_xor_sync(0xffffffff, mxB, 2));

        float mAn = fmaxf(mA, mxA), mBn = fmaxf(mB, mxB);
        float cA = __expf(mA - mAn), cB = __expf(mB - mBn);
        mA = mAn; mB = mBn;

        float sumA = 0.f, sumB = 0.f;
        #pragma unroll
        for (int ni = 0; ni < 4; ni++) {
            sAcc[ni][0] = __expf(sAcc[ni][0] - mA);
            sAcc[ni][1] = __expf(sAcc[ni][1] - mA);
            sAcc[ni][2] = __expf(sAcc[ni][2] - mB);
            sAcc[ni][3] = __expf(sAcc[ni][3] - mB);
            sumA += sAcc[ni][0] + sAcc[ni][1];
            sumB += sAcc[ni][2] + sAcc[ni][3];
        }
        sumA += __shfl_xor_sync(0xffffffff, sumA, 1);
        sumA += __shfl_xor_sync(0xffffffff, sumA, 2);
        sumB += __shfl_xor_sync(0xffffffff, sumB, 1);
        sumB += __shfl_xor_sync(0xffffffff, sumB, 2);
        lA = lA * cA + sumA;
        lB = lB * cB + sumB;

        #pragma unroll
        for (int t2 = 0; t2 < 16; t2++) {
            oAcc[t2][0] *= cA; oAcc[t2][1] *= cA;
            oAcc[t2][2] *= cB; oAcc[t2][3] *= cB;
        }

        // ---- pack P (16x32) into hi/lo A-fragments, register-only ----
        uint32_t phi[2][4], plo[2][4];
        #pragma unroll
        for (int j2 = 0; j2 < 2; j2++) {
            pack_hilo(sAcc[2*j2][0],   sAcc[2*j2][1],   phi[j2][0], plo[j2][0]);
            pack_hilo(sAcc[2*j2][2],   sAcc[2*j2][3],   phi[j2][1], plo[j2][1]);
            pack_hilo(sAcc[2*j2+1][0], sAcc[2*j2+1][1], phi[j2][2], plo[j2][2]);
            pack_hilo(sAcc[2*j2+1][2], sAcc[2*j2+1][3], phi[j2][3], plo[j2][3]);
        }

        // ---- O += (Phi Vhi + Plo Vhi + Phi Vlo) ----
        #pragma unroll
        for (int j2 = 0; j2 < 2; j2++) {
            int key0 = j2 * 16;
            #pragma unroll
            for (int nb = 0; nb < 8; nb++) {
                uint32_t vh[4], vl[4];
                uint32_t voff = (key0 + (lane & 15)) * AROWB
                              + (nb * 16 + ((lane >> 4) << 3)) * 2;
                ldsm_x4_t(vh, VhiS + voff);
                ldsm_x4_t(vl, VloS + voff);
                mma_bf16(oAcc[2*nb],   phi[j2], vh);
                mma_bf16(oAcc[2*nb],   plo[j2], vh);
                mma_bf16(oAcc[2*nb],   phi[j2], vl);
                mma_bf16(oAcc[2*nb+1], phi[j2], vh + 2);
                mma_bf16(oAcc[2*nb+1], plo[j2], vh + 2);
                mma_bf16(oAcc[2*nb+1], phi[j2], vl + 2);
            }
        }
        __syncthreads();
    }

    // ---- epilogue: normalize, write to [B,S,D] (head-contiguous) ----
    float invA = 1.0f / lA, invB = 1.0f / lB;
    int rA = qBase + m0 + (lane >> 2);
    int rB = rA + 8;
    float* outA = O + ((size_t)(b * SEQ + rA)) * D_MODEL + h * HD;
    float* outB = O + ((size_t)(b * SEQ + rB)) * D_MODEL + h * HD;
    #pragma unroll
    for (int t2 = 0; t2 < 16; t2++) {
        int cn = t2 * 8 + (lane & 3) * 2;
        float2 oa, ob;
        oa.x = oAcc[t2][0] * invA; oa.y = oAcc[t2][1] * invA;
        ob.x = oAcc[t2][2] * invB; ob.y = oAcc[t2][3] * invB;
        *(float2*)(outA + cn) = oa;
        *(float2*)(outB + cn) = ob;
    }
}

// ---------------- launch ----------------
extern "C" void kernel_launch(void* const* d_in, const int* in_sizes, int n_in,
                              void* d_out, int out_size)
{
    const float* x  = (const float*)d_in[0];
    const float* Wq = (const float*)d_in[1];
    const float* bq = (const float*)d_in[2];
    const float* Wk = (const float*)d_in[3];
    const float* bk = (const float*)d_in[4];
    const float* Wv = (const float*)d_in[5];
    const float* bv = (const float*)d_in[6];
    const float* Wo = (const float*)d_in[7];
    const float* bo = (const float*)d_in[8];
    float* out = (float*)d_out;

    float* scratch = nullptr;
    cudaGetSymbolAddress((void**)&scratch, g_scratch);
    const size_t NMe = (size_t)MROWS * D_MODEL;
    float* Qlin = scratch + 0 * NMe;
    float* Klin = scratch + 1 * NMe;
    float* Vlin = scratch + 2 * NMe;
    float* AO   = scratch + 3 * NMe;

    __nv_bfloat16* bfp = nullptr;
    cudaGetSymbolAddress((void**)&bfp, g_bf16);
    const size_t XH = (size_t)MROWS * KTOT;
    const size_t WH = (size_t)D_MODEL * KTOT;
    __nv_bfloat16* Xhat  = bfp;
    __nv_bfloat16* AOhat = bfp + XH;
    __nv_bfloat16* WqH   = bfp + 2 * XH;
    __nv_bfloat16* WkH   = WqH + WH;
    __nv_bfloat16* WvH   = WkH + WH;
    __nv_bfloat16* WoH   = WvH + WH;

    __nv_bfloat16* ap = nullptr;
    cudaGetSymbolAddress((void**)&ap, g_attn);
    const size_t AH = (size_t)BHS * HD;
    __nv_bfloat16* Qhi = ap + 0 * AH;
    __nv_bfloat16* Qlo = ap + 1 * AH;
    __nv_bfloat16* Khi = ap + 2 * AH;
    __nv_bfloat16* Klo = ap + 3 * AH;
    __nv_bfloat16* Vhi = ap + 4 * AH;
    __nv_bfloat16* Vlo = ap + 5 * AH;

    cudaFuncSetAttribute(gemm_mma_kernel, cudaFuncAttributeMaxDynamicSharedMemorySize,
                         GEMM_SMEM);
    cudaFuncSetAttribute(attn_mma_kernel, cudaFuncAttributeMaxDynamicSharedMemorySize,
                         ATTN_SMEM);

    // split operands to 3-term bf16
    split_kernel<<<(MROWS * D_MODEL) / 256, 256>>>(x,  Xhat, 0);
    split_kernel<<<(D_MODEL * D_MODEL) / 256, 256>>>(Wq, WqH, 1);
    split_kernel<<<(D_MODEL * D_MODEL) / 256, 256>>>(Wk, WkH, 1);
    split_kernel<<<(D_MODEL * D_MODEL) / 256, 256>>>(Wv, WvH, 1);
    split_kernel<<<(D_MODEL * D_MODEL) / 256, 256>>>(Wo, WoH, 1);

    dim3 ggrid(D_MODEL / BN, MROWS / BM);   // (16, 32)
    gemm_mma_kernel<<<ggrid, 256, GEMM_SMEM>>>(Xhat, WqH, bq, Qlin, D_MODEL);
    gemm_mma_kernel<<<ggrid, 256, GEMM_SMEM>>>(Xhat, WkH, bk, Klin, D_MODEL);
    gemm_mma_kernel<<<ggrid, 256, GEMM_SMEM>>>(Xhat, WvH, bv, Vlin, D_MODEL);

    int total = BATCH * NHEADS * SEQ * HD;
    rope_split_kernel<<<total / 256, 256>>>(Qlin, Klin, Vlin,
                                            Qhi, Qlo, Khi, Klo, Vhi, Vlo);

    attn_mma_kernel<<<dim3(SEQ / ATQ, NHEADS, BATCH), ATHR, ATTN_SMEM>>>(
        Qhi, Qlo, Khi, Klo, Vhi, Vlo, AO);

    split_kernel<<<(MROWS * D_MODEL) / 256, 256>>>(AO, AOhat, 0);
    gemm_mma_kernel<<<ggrid, 256, GEMM_SMEM>>>(AOhat, WoH, bo, out, D_MODEL);
}

// round 15
// speedup vs baseline: 2.0834x; 1.8940x over previous
#include <cuda_runtime.h>
#include <cuda_fp16.h>
#include <cuda_bf16.h>
#include <math.h>
#include <stdint.h>

// ---------------- problem constants ----------------
#define D_MODEL 2048
#define NHEADS  16
#define HD      128
#define BATCH   2
#define SEQ     2048
#define MROWS   (BATCH*SEQ)   // 4096
#define KT2     (2*D_MODEL)   // 4096 (2-term fp16 split along K, GEMM only)
#define BHS     (BATCH*NHEADS*SEQ)   // 65536

// fp32 scratch: Qlin,Klin,Vlin,AO
__device__ float g_scratch[4ULL * MROWS * D_MODEL];
// fp16 GEMM operands: Xhat[4096,4096], AOhat[4096,4096], 4x What[2048,4096]
__device__ __half g_half[2ULL * MROWS * KT2 + 4ULL * D_MODEL * KT2];
// bf16 attention operands: Qhi,Qlo,Khi,Klo,Vhi,Vlo each [B,H,S,HD]
__device__ __nv_bfloat16 g_attn[6ULL * BHS * HD];

// ---------------- PTX helpers (portable: sm_75/80-era only) ----------------
__device__ __forceinline__ uint32_t smem_u32(const void* p) {
    uint32_t r;
    asm("{ .reg .u64 t; cvta.to.shared.u64 t, %1; cvt.u32.u64 %0, t; }"
        : "=r"(r) : "l"(p));
    return r;
}

__device__ __forceinline__ void cp16(uint32_t dst, const void* src) {
    asm volatile("cp.async.cg.shared.global [%0], [%1], 16;"
                 :: "r"(dst), "l"(src));
}

__device__ __forceinline__ void ldsm_x4(uint32_t* r, uint32_t addr) {
    asm volatile("ldmatrix.sync.aligned.m8n8.x4.shared.b16 {%0,%1,%2,%3}, [%4];"
                 : "=r"(r[0]), "=r"(r[1]), "=r"(r[2]), "=r"(r[3]) : "r"(addr));
}

__device__ __forceinline__ void ldsm_x4_t(uint32_t* r, uint32_t addr) {
    asm volatile("ldmatrix.sync.aligned.m8n8.x4.trans.shared.b16 {%0,%1,%2,%3}, [%4];"
                 : "=r"(r[0]), "=r"(r[1]), "=r"(r[2]), "=r"(r[3]) : "r"(addr));
}

__device__ __forceinline__ void mma_f16(float* d, const uint32_t* a, const uint32_t* b) {
    asm volatile(
        "mma.sync.aligned.m16n8k16.row.col.f32.f16.f16.f32 "
        "{%0,%1,%2,%3}, {%4,%5,%6,%7}, {%8,%9}, {%0,%1,%2,%3};"
        : "+f"(d[0]), "+f"(d[1]), "+f"(d[2]), "+f"(d[3])
        : "r"(a[0]), "r"(a[1]), "r"(a[2]), "r"(a[3]), "r"(b[0]), "r"(b[1]));
}

__device__ __forceinline__ void mma_bf16(float* d, const uint32_t* a, const uint32_t* b) {
    asm volatile(
        "mma.sync.aligned.m16n8k16.row.col.f32.bf16.bf16.f32 "
        "{%0,%1,%2,%3}, {%4,%5,%6,%7}, {%8,%9}, {%0,%1,%2,%3};"
        : "+f"(d[0]), "+f"(d[1]), "+f"(d[2]), "+f"(d[3])
        : "r"(a[0]), "r"(a[1]), "r"(a[2]), "r"(a[3]), "r"(b[0]), "r"(b[1]));
}

__device__ __forceinline__ void pack_hilo(float a, float b, uint32_t& hi, uint32_t& lo) {
    __nv_bfloat162 th, tl;
    th.x = __float2bfloat16(a);
    th.y = __float2bfloat16(b);
    tl.x = __float2bfloat16(a - __bfloat162float(th.x));
    tl.y = __float2bfloat16(b - __bfloat162float(th.y));
    hi = *(uint32_t*)&th;
    lo = *(uint32_t*)&tl;
}

// ---------------- split fp32 -> 2-term fp16 (GEMM operands) ----------------
// A-side (isW=0): [hi | lo]    W-side (isW=1): [hi | hi]
__global__ __launch_bounds__(256) void split_kernel(
    const float* __restrict__ in, __half* __restrict__ out, int isW)
{
    int idx = blockIdx.x * 256 + threadIdx.x;
    int r = idx >> 11;
    int k = idx & 2047;
    float v = in[idx];
    __half hi = __float2half(v);
    __half lo = __float2half(v - __half2float(hi));
    __half* o = out + (size_t)r * KT2;
    o[k] = hi;
    o[D_MODEL + k] = isW ? hi : lo;
}

// ---------------- mma.sync fp16 GEMM: C[M,N] = A @ B^T + bias ----------------
#define BM 128
#define BN 128
#define BK 32
#define NSTAGE 3
#define NT (KT2 / BK)                // 128
#define ROWB 80
#define A_BYTES (BM * ROWB)          // 10240
#define STAGE_BYTES (2 * BM * ROWB)  // 20480
#define GEMM_SMEM (NSTAGE * STAGE_BYTES)  // 61440

__global__ __launch_bounds__(256) void gemm_mma_kernel(
    const __half* __restrict__ A, const __half* __restrict__ B,
    const float* __restrict__ bias, float* __restrict__ C, int N)
{
    extern __shared__ __align__(128) char smraw[];
    const uint32_t smb = smem_u32(smraw);
    const int tid  = threadIdx.x;
    const int lane = tid & 31;
    const int wid  = tid >> 5;
    const int wm   = (wid >> 2) * 64;
    const int wn   = (wid & 3) * 32;
    const int rowBase = blockIdx.y * BM;
    const int colBase = blockIdx.x * BN;

    const char* Ag = (const char*)A + (size_t)rowBase * (KT2 * 2);
    const char* Bg = (const char*)B + (size_t)colBase * (KT2 * 2);

    float acc[4][4][4];
    #pragma unroll
    for (int mi = 0; mi < 4; mi++)
        #pragma unroll
        for (int ni = 0; ni < 4; ni++)
            #pragma unroll
            for (int u = 0; u < 4; u++) acc[mi][ni][u] = 0.f;

    const int lr0 = tid >> 2;
    const int lc  = (tid & 3) * 16;

    auto load_stage = [&](int kt) {
        if (kt < NT) {
            uint32_t base = smb + (kt % NSTAGE) * STAGE_BYTES;
            const size_t gk = (size_t)kt * 64;
            #pragma unroll
            for (int i = 0; i < 2; i++) {
                int r = lr0 + i * 64;
                cp16(base + r * ROWB + lc, Ag + (size_t)r * (KT2 * 2) + gk + lc);
            }
            #pragma unroll
            for (int i = 0; i < 2; i++) {
                int r = lr0 + i * 64;
                cp16(base + A_BYTES + r * ROWB + lc,
                     Bg + (size_t)r * (KT2 * 2) + gk + lc);
            }
        }
        asm volatile("cp.async.commit_group;" ::: "memory");
    };

    load_stage(0);
    load_stage(1);

    const int a_row  = lane & 15;
    const int a_half = (lane >> 4) * 16;
    const int b_row  = ((lane >> 4) << 3) + (lane & 7);
    const int b_half = ((lane >> 3) & 1) * 16;

    for (int kt = 0; kt < NT; kt++) {
        asm volatile("cp.async.wait_group %0;" :: "n"(NSTAGE - 2) : "memory");
        __syncthreads();
        load_stage(kt + NSTAGE - 1);

        uint32_t aBase = smb + (kt % NSTAGE) * STAGE_BYTES;
        uint32_t bBase = aBase + A_BYTES;

        #pragma unroll
        for (int j = 0; j < 2; j++) {
            uint32_t af[4][4];
            #pragma unroll
            for (int mi = 0; mi < 4; mi++)
                ldsm_x4(af[mi],
                        aBase + (wm + mi * 16 + a_row) * ROWB + j * 32 + a_half);
            uint32_t bf[2][4];
            #pragma unroll
            for (int nb = 0; nb < 2; nb++)
                ldsm_x4(bf[nb],
                        bBase + (wn + nb * 16 + b_row) * ROWB + j * 32 + b_half);
            #pragma unroll
            for (int mi = 0; mi < 4; mi++)
                #pragma unroll
                for (int ni = 0; ni < 4; ni++)
                    mma_f16(acc[mi][ni], af[mi], &bf[ni >> 1][(ni & 1) * 2]);
        }
        __syncthreads();
    }

    #pragma unroll
    for (int mi = 0; mi < 4; mi++) {
        int r0 = rowBase + wm + mi * 16 + (lane >> 2);
        #pragma unroll
        for (int ni = 0; ni < 4; ni++) {
            int cn = colBase + wn + ni * 8 + (lane & 3) * 2;
            float2 bv = *(const float2*)(bias + cn);
            float2 o0, o1;
            o0.x = acc[mi][ni][0] + bv.x; o0.y = acc[mi][ni][1] + bv.y;
            o1.x = acc[mi][ni][2] + bv.x; o1.y = acc[mi][ni][3] + bv.y;
            *(float2*)(C + (size_t)r0 * N + cn) = o0;
            *(float2*)(C + (size_t)(r0 + 8) * N + cn) = o1;
        }
    }
}

// ---------------- RoPE (reference-exact) -> bf16 hi/lo Q,K,V [B,H,S,HD] ----------------
__global__ __launch_bounds__(256) void rope_split_kernel(
    const float* __restrict__ Qlin, const float* __restrict__ Klin,
    const float* __restrict__ Vlin,
    __nv_bfloat16* __restrict__ Qhi, __nv_bfloat16* __restrict__ Qlo,
    __nv_bfloat16* __restrict__ Khi, __nv_bfloat16* __restrict__ Klo,
    __nv_bfloat16* __restrict__ Vhi, __nv_bfloat16* __restrict__ Vlo)
{
    int idx = blockIdx.x * blockDim.x + threadIdx.x;   // [B,H,S,HD] flat
    int d = idx & (HD - 1);
    int s = (idx >> 7) & (SEQ - 1);
    int h = (idx >> 18) & (NHEADS - 1);
    int b = idx >> 22;

    size_t src = ((size_t)(b * SEQ + s)) * D_MODEL + h * HD + d;
    int j = d & 63;
    float invf = expf(-(float)j * (9.210340371976184f / 64.0f));
    float ang  = (float)s * invf;
    float e    = (d < 64) ? sinf(ang) : cosf(ang);     // emb (reference quirk)
    float ce   = cosf(e);
    float se   = sinf(e);

    size_t srcP = (d < 64) ? src + 64 : src - 64;
    float sgn   = (d < 64) ? -1.0f : 1.0f;

    float q = Qlin[src], qp = Qlin[srcP];
    float k = Klin[src], kp = Klin[srcP];
    float qr = fmaf(q, ce, sgn * qp * se);
    float kr = fmaf(k, ce, sgn * kp * se);
    float v  = Vlin[src];

    __nv_bfloat16 qh = __float2bfloat16(qr);
    __nv_bfloat16 kh = __float2bfloat16(kr);
    __nv_bfloat16 vh = __float2bfloat16(v);
    Qhi[idx] = qh; Qlo[idx] = __float2bfloat16(qr - __bfloat162float(qh));
    Khi[idx] = kh; Klo[idx] = __float2bfloat16(kr - __bfloat162float(kh));
    Vhi[idx] = vh; Vlo[idx] = __float2bfloat16(v  - __bfloat162float(vh));
}

// ---------------- tensor-core flash attention (bf16 3-term, R9 2272us-proven) ----------------
#define ATQ 128
#define ATK 64
#define AROWB 272
#define Q_ARR (ATQ * AROWB)            // 34816
#define KV_ARR (ATK * AROWB)           // 17408
#define KV_STAGE (4 * KV_ARR)          // 69632 (Khi,Klo,Vhi,Vlo)
#define KV_OFF (2 * Q_ARR)             // 69632
#define ATTN_SMEM (KV_OFF + 2 * KV_STAGE)  // 208896
#define NKT (SEQ / ATK)                // 32

__global__ __launch_bounds__(256) void attn_mma_kernel(
    const __nv_bfloat16* __restrict__ Qhi, const __nv_bfloat16* __restrict__ Qlo,
    const __nv_bfloat16* __restrict__ Khi, const __nv_bfloat16* __restrict__ Klo,
    const __nv_bfloat16* __restrict__ Vhi, const __nv_bfloat16* __restrict__ Vlo,
    float* __restrict__ O)
{
    extern __shared__ __align__(128) char smraw[];
    const uint32_t smb = smem_u32(smraw);
    const int tid  = threadIdx.x;
    const int lane = tid & 31;
    const int wid  = tid >> 5;
    const int qBase = blockIdx.x * ATQ;
    const int h = blockIdx.y;
    const int b = blockIdx.z;
    const size_t bh = (size_t)b * NHEADS + h;

    const char* Qhg = (const char*)Qhi + (bh * SEQ + qBase) * (HD * 2);
    const char* Qlg = (const char*)Qlo + (bh * SEQ + qBase) * (HD * 2);
    const char* Khg = (const char*)Khi + bh * SEQ * (HD * 2);
    const char* Klg = (const char*)Klo + bh * SEQ * (HD * 2);
    const char* Vhg = (const char*)Vhi + bh * SEQ * (HD * 2);
    const char* Vlg = (const char*)Vlo + bh * SEQ * (HD * 2);

    #pragma unroll
    for (int i = 0; i < 16; i++) {
        int idx = tid + i * 256;
        int arr = idx >> 11;
        int r   = (idx >> 4) & 127;
        int c   = (idx & 15) * 16;
        const char* sp = arr ? Qlg : Qhg;
        cp16(smb + arr * Q_ARR + r * AROWB + c, sp + (size_t)r * 256 + c);
    }
    asm volatile("cp.async.commit_group;" ::: "memory");

    auto loadKV = [&](int kt) {
        int s = kt & 1;
        #pragma unroll
        for (int i = 0; i < 16; i++) {
            int idx = tid + i * 256;
            int arr = idx >> 10;
            int r   = (idx >> 4) & 63;
            int c   = (idx & 15) * 16;
            const char* sp = (arr == 0) ? Khg : (arr == 1) ? Klg
                           : (arr == 2) ? Vhg : Vlg;
            cp16(smb + KV_OFF + s * KV_STAGE + arr * KV_ARR + r * AROWB + c,
                 sp + (size_t)(kt * ATK + r) * 256 + c);
        }
        asm volatile("cp.async.commit_group;" ::: "memory");
    };

    loadKV(0);

    float oAcc[16][4];
    #pragma unroll
    for (int t2 = 0; t2 < 16; t2++)
        #pragma unroll
        for (int u = 0; u < 4; u++) oAcc[t2][u] = 0.f;
    float mA = -INFINITY, mB = -INFINITY, lA = 0.f, lB = 0.f;

    const int m0 = wid * 16;
    const int a_row  = lane & 15;
    const int a_halfB = (lane >> 4) * 16;
    const int b_row  = ((lane >> 4) << 3) + (lane & 7);
    const int b_halfB = ((lane >> 3) & 1) * 16;
    const float SCALE = 0.08838834764831845f;

    for (int kt = 0; kt < NKT; kt++) {
        if (kt + 1 < NKT) {
            loadKV(kt + 1);
            asm volatile("cp.async.wait_group 1;" ::: "memory");
        } else {
            asm volatile("cp.async.wait_group 0;" ::: "memory");
        }
        __syncthreads();

        const uint32_t kb   = smb + KV_OFF + (kt & 1) * KV_STAGE;
        const uint32_t KhiS = kb;
        const uint32_t KloS = kb + KV_ARR;
        const uint32_t VhiS = kb + 2 * KV_ARR;
        const uint32_t VloS = kb + 3 * KV_ARR;

        float sAcc[8][4];
        #pragma unroll
        for (int ni = 0; ni < 8; ni++)
            #pragma unroll
            for (int u = 0; u < 4; u++) sAcc[ni][u] = 0.f;

        #pragma unroll
        for (int j = 0; j < 8; j++) {
            uint32_t ah[4], al[4];
            uint32_t aoff = (m0 + a_row) * AROWB + j * 32 + a_halfB;
            ldsm_x4(ah, smb + aoff);
            ldsm_x4(al, smb + Q_ARR + aoff);
            uint32_t bh_[4][4], bl_[4][4];
            #pragma unroll
            for (int nb = 0; nb < 4; nb++) {
                uint32_t boff = (nb * 16 + b_row) * AROWB + j * 32 + b_halfB;
                ldsm_x4(bh_[nb], KhiS + boff);
                ldsm_x4(bl_[nb], KloS + boff);
            }
            #pragma unroll
            for (int ni = 0; ni < 8; ni++) {
                const uint32_t* Bh = &bh_[ni >> 1][(ni & 1) * 2];
                const uint32_t* Bl = &bl_[ni >> 1][(ni & 1) * 2];
                mma_bf16(sAcc[ni], ah, Bh);
                mma_bf16(sAcc[ni], al, Bh);
                mma_bf16(sAcc[ni], ah, Bl);
            }
        }

        float mxA = -INFINITY, mxB = -INFINITY;
        #pragma unroll
        for (int ni = 0; ni < 8; ni++) {
            #pragma unroll
            for (int u = 0; u < 4; u++) sAcc[ni][u] *= SCALE;
            mxA = fmaxf(mxA, fmaxf(sAcc[ni][0], sAcc[ni][1]));
            mxB = fmaxf(mxB, fmaxf(sAcc[ni][2], sAcc[ni][3]));
        }
        mxA = fmaxf(mxA, __shfl_xor_sync(0xffffffff, mxA, 1));
        mxA = fmaxf(mxA, __shfl_xor_sync(0xffffffff, mxA, 2));
        mxB = fmaxf(mxB, __shfl_xor_sync(0xffffffff, mxB, 1));
        mxB = fmaxf(mxB, __shfl_xor_sync(0xffffffff, mxB, 2));

        float mAn = fmaxf(mA, mxA), mBn = fmaxf(mB, mxB);
        float cA = __expf(mA - mAn), cB = __expf(mB - mBn);
        mA = mAn; mB = mBn;

        float sumA = 0.f, sumB = 0.f;
        #pragma unroll
        for (int ni = 0; ni < 8; ni++) {
            sAcc[ni][0] = __expf(sAcc[ni][0] - mA);
            sAcc[ni][1] = __expf(sAcc[ni][1] - mA);
            sAcc[ni][2] = __expf(sAcc[ni][2] - mB);
            sAcc[ni][3] = __expf(sAcc[ni][3] - mB);
            sumA += sAcc[ni][0] + sAcc[ni][1];
            sumB += sAcc[ni][2] + sAcc[ni][3];
        }
        sumA += __shfl_xor_sync(0xffffffff, sumA, 1);
        sumA += __shfl_xor_sync(0xffffffff, sumA, 2);
        sumB += __shfl_xor_sync(0xffffffff, sumB, 1);
        sumB += __shfl_xor_sync(0xffffffff, sumB, 2);
        lA = lA * cA + sumA;
        lB = lB * cB + sumB;

        #pragma unroll
        for (int t2 = 0; t2 < 16; t2++) {
            oAcc[t2][0] *= cA; oAcc[t2][1] *= cA;
            oAcc[t2][2] *= cB; oAcc[t2][3] *= cB;
        }

        uint32_t phi[4][4], plo[4][4];
        #pragma unroll
        for (int j2 = 0; j2 < 4; j2++) {
            pack_hilo(sAcc[2*j2][0],   sAcc[2*j2][1],   phi[j2][0], plo[j2][0]);
            pack_hilo(sAcc[2*j2][2],   sAcc[2*j2][3],   phi[j2][1], plo[j2][1]);
            pack_hilo(sAcc[2*j2+1][0], sAcc[2*j2+1][1], phi[j2][2], plo[j2][2]);
            pack_hilo(sAcc[2*j2+1][2], sAcc[2*j2+1][3], phi[j2][3], plo[j2][3]);
        }

        #pragma unroll
        for (int j2 = 0; j2 < 4; j2++) {
            int key0 = j2 * 16;
            #pragma unroll
            for (int nb = 0; nb < 8; nb++) {
                uint32_t vh[4], vl[4];
                uint32_t voff = (key0 + (lane & 15)) * AROWB
                              + (nb * 16 + ((lane >> 4) << 3)) * 2;
                ldsm_x4_t(vh, VhiS + voff);
                ldsm_x4_t(vl, VloS + voff);
                mma_bf16(oAcc[2*nb],   phi[j2], vh);
                mma_bf16(oAcc[2*nb],   plo[j2], vh);
                mma_bf16(oAcc[2*nb],   phi[j2], vl);
                mma_bf16(oAcc[2*nb+1], phi[j2], vh + 2);
                mma_bf16(oAcc[2*nb+1], plo[j2], vh + 2);
                mma_bf16(oAcc[2*nb+1], phi[j2], vl + 2);
            }
        }
        __syncthreads();
    }

    float invA = 1.0f / lA, invB = 1.0f / lB;
    int rA = qBase + m0 + (lane >> 2);
    int rB = rA + 8;
    float* outA = O + ((size_t)(b * SEQ + rA)) * D_MODEL + h * HD;
    float* outB = O + ((size_t)(b * SEQ + rB)) * D_MODEL + h * HD;
    #pragma unroll
    for (int t2 = 0; t2 < 16; t2++) {
        int cn = t2 * 8 + (lane & 3) * 2;
        float2 oa, ob;
        oa.x = oAcc[t2][0] * invA; oa.y = oAcc[t2][1] * invA;
        ob.x = oAcc[t2][2] * invB; ob.y = oAcc[t2][3] * invB;
        *(float2*)(outA + cn) = oa;
        *(float2*)(outB + cn) = ob;
    }
}

// ---------------- launch ----------------
extern "C" void kernel_launch(void* const* d_in, const int* in_sizes, int n_in,
                              void* d_out, int out_size)
{
    const float* x  = (const float*)d_in[0];
    const float* Wq = (const float*)d_in[1];
    const float* bq = (const float*)d_in[2];
    const float* Wk = (const float*)d_in[3];
    const float* bk = (const float*)d_in[4];
    const float* Wv = (const float*)d_in[5];
    const float* bv = (const float*)d_in[6];
    const float* Wo = (const float*)d_in[7];
    const float* bo = (const float*)d_in[8];
    float* out = (float*)d_out;

    float* scratch = nullptr;
    cudaGetSymbolAddress((void**)&scratch, g_scratch);
    const size_t NMe = (size_t)MROWS * D_MODEL;
    float* Qlin = scratch + 0 * NMe;
    float* Klin = scratch + 1 * NMe;
    float* Vlin = scratch + 2 * NMe;
    float* AO   = scratch + 3 * NMe;

    __half* hp = nullptr;
    cudaGetSymbolAddress((void**)&hp, g_half);
    const size_t XH = (size_t)MROWS * KT2;
    const size_t WH = (size_t)D_MODEL * KT2;
    __half* Xhat  = hp;
    __half* AOhat = hp + XH;
    __half* WqH   = hp + 2 * XH;
    __half* WkH   = WqH + WH;
    __half* WvH   = WkH + WH;
    __half* WoH   = WvH + WH;

    __nv_bfloat16* ap = nullptr;
    cudaGetSymbolAddress((void**)&ap, g_attn);
    const size_t AH = (size_t)BHS * HD;
    __nv_bfloat16* Qhi = ap + 0 * AH;
    __nv_bfloat16* Qlo = ap + 1 * AH;
    __nv_bfloat16* Khi = ap + 2 * AH;
    __nv_bfloat16* Klo = ap + 3 * AH;
    __nv_bfloat16* Vhi = ap + 4 * AH;
    __nv_bfloat16* Vlo = ap + 5 * AH;

    cudaFuncSetAttribute(gemm_mma_kernel, cudaFuncAttributeMaxDynamicSharedMemorySize,
                         GEMM_SMEM);
    cudaFuncSetAttribute(attn_mma_kernel, cudaFuncAttributeMaxDynamicSharedMemorySize,
                         ATTN_SMEM);

    // split operands to 2-term fp16 (GEMM)
    split_kernel<<<(MROWS * D_MODEL) / 256, 256>>>(x,  Xhat, 0);
    split_kernel<<<(D_MODEL * D_MODEL) / 256, 256>>>(Wq, WqH, 1);
    split_kernel<<<(D_MODEL * D_MODEL) / 256, 256>>>(Wk, WkH, 1);
    split_kernel<<<(D_MODEL * D_MODEL) / 256, 256>>>(Wv, WvH, 1);
    split_kernel<<<(D_MODEL * D_MODEL) / 256, 256>>>(Wo, WoH, 1);

    dim3 ggrid(D_MODEL / BN, MROWS / BM);   // (16, 32)
    gemm_mma_kernel<<<ggrid, 256, GEMM_SMEM>>>(Xhat, WqH, bq, Qlin, D_MODEL);
    gemm_mma_kernel<<<ggrid, 256, GEMM_SMEM>>>(Xhat, WkH, bk, Klin, D_MODEL);
    gemm_mma_kernel<<<ggrid, 256, GEMM_SMEM>>>(Xhat, WvH, bv, Vlin, D_MODEL);

    int total = BATCH * NHEADS * SEQ * HD;
    rope_split_kernel<<<total / 256, 256>>>(Qlin, Klin, Vlin,
                                            Qhi, Qlo, Khi, Klo, Vhi, Vlo);

    attn_mma_kernel<<<dim3(SEQ / ATQ, NHEADS, BATCH), 256, ATTN_SMEM>>>(
        Qhi, Qlo, Khi, Klo, Vhi, Vlo, AO);

    split_kernel<<<(MROWS * D_MODEL) / 256, 256>>>(AO, AOhat, 0);
    gemm_mma_kernel<<<ggrid, 256, GEMM_SMEM>>>(AOhat, WoH, bo, out, D_MODEL);
}

// round 16
// speedup vs baseline: 2.4013x; 1.1526x over previous
#include <cuda_runtime.h>
#include <cuda_fp16.h>
#include <math.h>
#include <stdint.h>

// ---------------- problem constants ----------------
#define D_MODEL 2048
#define NHEADS  16
#define HD      128
#define BATCH   2
#define SEQ     2048
#define MROWS   (BATCH*SEQ)   // 4096
#define KT2     (2*D_MODEL)   // 4096 (2-term fp16 split along K)
#define BHS     (BATCH*NHEADS*SEQ)   // 65536

// fp32 scratch: Qlin,Klin,Vlin
__device__ float g_scratch[3ULL * MROWS * D_MODEL];
// fp16 GEMM operands: Xhat[4096,4096], AOhat[4096,4096], 4x What[2048,4096]
__device__ __half g_half[2ULL * MROWS * KT2 + 4ULL * D_MODEL * KT2];
// fp16 attention operands: Qhi,Qlo,Khi,Vhi each [B,H,S,HD]
__device__ __half g_attn[4ULL * BHS * HD];

// ---------------- PTX helpers (portable: sm_75/80-era only) ----------------
__device__ __forceinline__ uint32_t smem_u32(const void* p) {
    uint32_t r;
    asm("{ .reg .u64 t; cvta.to.shared.u64 t, %1; cvt.u32.u64 %0, t; }"
        : "=r"(r) : "l"(p));
    return r;
}

__device__ __forceinline__ void cp16(uint32_t dst, const void* src) {
    asm volatile("cp.async.cg.shared.global [%0], [%1], 16;"
                 :: "r"(dst), "l"(src));
}

__device__ __forceinline__ void ldsm_x4(uint32_t* r, uint32_t addr) {
    asm volatile("ldmatrix.sync.aligned.m8n8.x4.shared.b16 {%0,%1,%2,%3}, [%4];"
                 : "=r"(r[0]), "=r"(r[1]), "=r"(r[2]), "=r"(r[3]) : "r"(addr));
}

__device__ __forceinline__ void ldsm_x4_t(uint32_t* r, uint32_t addr) {
    asm volatile("ldmatrix.sync.aligned.m8n8.x4.trans.shared.b16 {%0,%1,%2,%3}, [%4];"
                 : "=r"(r[0]), "=r"(r[1]), "=r"(r[2]), "=r"(r[3]) : "r"(addr));
}

__device__ __forceinline__ void mma_f16(float* d, const uint32_t* a, const uint32_t* b) {
    asm volatile(
        "mma.sync.aligned.m16n8k16.row.col.f32.f16.f16.f32 "
        "{%0,%1,%2,%3}, {%4,%5,%6,%7}, {%8,%9}, {%0,%1,%2,%3};"
        : "+f"(d[0]), "+f"(d[1]), "+f"(d[2]), "+f"(d[3])
        : "r"(a[0]), "r"(a[1]), "r"(a[2]), "r"(a[3]), "r"(b[0]), "r"(b[1]));
}

__device__ __forceinline__ void pack_hilo(float a, float b, uint32_t& hi, uint32_t& lo) {
    __half2 th, tl;
    th.x = __float2half(a);
    th.y = __float2half(b);
    tl.x = __float2half(a - __half2float(th.x));
    tl.y = __float2half(b - __half2float(th.y));
    hi = *(uint32_t*)&th;
    lo = *(uint32_t*)&tl;
}

// ---------------- split fp32 -> 2-term fp16 ----------------
// A-side (isW=0): [hi | lo]    W-side (isW=1): [hi | hi]
__global__ __launch_bounds__(256) void split_kernel(
    const float* __restrict__ in, __half* __restrict__ out, int isW)
{
    int idx = blockIdx.x * 256 + threadIdx.x;
    int r = idx >> 11;
    int k = idx & 2047;
    float v = in[idx];
    __half hi = __float2half(v);
    __half lo = __float2half(v - __half2float(hi));
    __half* o = out + (size_t)r * KT2;
    o[k] = hi;
    o[D_MODEL + k] = isW ? hi : lo;
}

// ---------------- mma.sync fp16 GEMM: C[M,N] = A @ B^T + bias (R14-proven) ----------------
#define BM 128
#define BN 128
#define BK 32
#define NSTAGE 3
#define NT (KT2 / BK)                // 128
#define ROWB 80
#define A_BYTES (BM * ROWB)          // 10240
#define STAGE_BYTES (2 * BM * ROWB)  // 20480
#define GEMM_SMEM (NSTAGE * STAGE_BYTES)  // 61440

__global__ __launch_bounds__(256) void gemm_mma_kernel(
    const __half* __restrict__ A, const __half* __restrict__ B,
    const float* __restrict__ bias, float* __restrict__ C, int N)
{
    extern __shared__ __align__(128) char smraw[];
    const uint32_t smb = smem_u32(smraw);
    const int tid  = threadIdx.x;
    const int lane = tid & 31;
    const int wid  = tid >> 5;
    const int wm   = (wid >> 2) * 64;
    const int wn   = (wid & 3) * 32;
    const int rowBase = blockIdx.y * BM;
    const int colBase = blockIdx.x * BN;

    const char* Ag = (const char*)A + (size_t)rowBase * (KT2 * 2);
    const char* Bg = (const char*)B + (size_t)colBase * (KT2 * 2);

    float acc[4][4][4];
    #pragma unroll
    for (int mi = 0; mi < 4; mi++)
        #pragma unroll
        for (int ni = 0; ni < 4; ni++)
            #pragma unroll
            for (int u = 0; u < 4; u++) acc[mi][ni][u] = 0.f;

    const int lr0 = tid >> 2;
    const int lc  = (tid & 3) * 16;

    auto load_stage = [&](int kt) {
        if (kt < NT) {
            uint32_t base = smb + (kt % NSTAGE) * STAGE_BYTES;
            const size_t gk = (size_t)kt * 64;
            #pragma unroll
            for (int i = 0; i < 2; i++) {
                int r = lr0 + i * 64;
                cp16(base + r * ROWB + lc, Ag + (size_t)r * (KT2 * 2) + gk + lc);
            }
            #pragma unroll
            for (int i = 0; i < 2; i++) {
                int r = lr0 + i * 64;
                cp16(base + A_BYTES + r * ROWB + lc,
                     Bg + (size_t)r * (KT2 * 2) + gk + lc);
            }
        }
        asm volatile("cp.async.commit_group;" ::: "memory");
    };

    load_stage(0);
    load_stage(1);

    const int a_row  = lane & 15;
    const int a_half = (lane >> 4) * 16;
    const int b_row  = ((lane >> 4) << 3) + (lane & 7);
    const int b_half = ((lane >> 3) & 1) * 16;

    for (int kt = 0; kt < NT; kt++) {
        asm volatile("cp.async.wait_group %0;" :: "n"(NSTAGE - 2) : "memory");
        __syncthreads();
        load_stage(kt + NSTAGE - 1);

        uint32_t aBase = smb + (kt % NSTAGE) * STAGE_BYTES;
        uint32_t bBase = aBase + A_BYTES;

        #pragma unroll
        for (int j = 0; j < 2; j++) {
            uint32_t af[4][4];
            #pragma unroll
            for (int mi = 0; mi < 4; mi++)
                ldsm_x4(af[mi],
                        aBase + (wm + mi * 16 + a_row) * ROWB + j * 32 + a_half);
            uint32_t bf[2][4];
            #pragma unroll
            for (int nb = 0; nb < 2; nb++)
                ldsm_x4(bf[nb],
                        bBase + (wn + nb * 16 + b_row) * ROWB + j * 32 + b_half);
            #pragma unroll
            for (int mi = 0; mi < 4; mi++)
                #pragma unroll
                for (int ni = 0; ni < 4; ni++)
                    mma_f16(acc[mi][ni], af[mi], &bf[ni >> 1][(ni & 1) * 2]);
        }
        __syncthreads();
    }

    #pragma unroll
    for (int mi = 0; mi < 4; mi++) {
        int r0 = rowBase + wm + mi * 16 + (lane >> 2);
        #pragma unroll
        for (int ni = 0; ni < 4; ni++) {
            int cn = colBase + wn + ni * 8 + (lane & 3) * 2;
            float2 bv = *(const float2*)(bias + cn);
            float2 o0, o1;
            o0.x = acc[mi][ni][0] + bv.x; o0.y = acc[mi][ni][1] + bv.y;
            o1.x = acc[mi][ni][2] + bv.x; o1.y = acc[mi][ni][3] + bv.y;
            *(float2*)(C + (size_t)r0 * N + cn) = o0;
            *(float2*)(C + (size_t)(r0 + 8) * N + cn) = o1;
        }
    }
}

// ---------------- RoPE (reference-exact) -> fp16 Qhi,Qlo,Khi,Vhi [B,H,S,HD] ----------------
__global__ __launch_bounds__(256) void rope_split_kernel(
    const float* __restrict__ Qlin, const float* __restrict__ Klin,
    const float* __restrict__ Vlin,
    __half* __restrict__ Qhi, __half* __restrict__ Qlo,
    __half* __restrict__ Khi, __half* __restrict__ Vhi)
{
    int idx = blockIdx.x * blockDim.x + threadIdx.x;   // [B,H,S,HD] flat
    int d = idx & (HD - 1);
    int s = (idx >> 7) & (SEQ - 1);
    int h = (idx >> 18) & (NHEADS - 1);
    int b = idx >> 22;

    size_t src = ((size_t)(b * SEQ + s)) * D_MODEL + h * HD + d;
    int j = d & 63;
    float invf = expf(-(float)j * (9.210340371976184f / 64.0f));
    float ang  = (float)s * invf;
    float e    = (d < 64) ? sinf(ang) : cosf(ang);     // emb (reference quirk)
    float ce   = cosf(e);
    float se   = sinf(e);

    size_t srcP = (d < 64) ? src + 64 : src - 64;
    float sgn   = (d < 64) ? -1.0f : 1.0f;

    float q = Qlin[src], qp = Qlin[srcP];
    float k = Klin[src], kp = Klin[srcP];
    float qr = fmaf(q, ce, sgn * qp * se);
    float kr = fmaf(k, ce, sgn * kp * se);

    __half qh = __float2half(qr);
    Qhi[idx] = qh;
    Qlo[idx] = __float2half(qr - __half2float(qh));
    Khi[idx] = __float2half(kr);
    Vhi[idx] = __float2half(Vlin[src]);
}

// ---------------- tensor-core flash attention (fp16 2-term, fused AO split) ----------------
#define ATQ 128
#define ATK 64
#define AROWB 272
#define Q_ARR (ATQ * AROWB)            // 34816
#define KV_ARR (ATK * AROWB)           // 17408
#define KV_STAGE (2 * KV_ARR)          // 34816 (Khi, Vhi)
#define KV_OFF (2 * Q_ARR)             // 69632
#define ATTN_SMEM (KV_OFF + 2 * KV_STAGE)  // 139264
#define NKT (SEQ / ATK)                // 32

__global__ __launch_bounds__(256) void attn_mma_kernel(
    const __half* __restrict__ Qhi, const __half* __restrict__ Qlo,
    const __half* __restrict__ Khi, const __half* __restrict__ Vhi,
    __half* __restrict__ AOhat)     // [MROWS, KT2] in [hi | lo] layout
{
    extern __shared__ __align__(128) char smraw[];
    const uint32_t smb = smem_u32(smraw);
    const int tid  = threadIdx.x;
    const int lane = tid & 31;
    const int wid  = tid >> 5;
    const int qBase = blockIdx.x * ATQ;
    const int h = blockIdx.y;
    const int b = blockIdx.z;
    const size_t bh = (size_t)b * NHEADS + h;

    const char* Qhg = (const char*)Qhi + (bh * SEQ + qBase) * (HD * 2);
    const char* Qlg = (const char*)Qlo + (bh * SEQ + qBase) * (HD * 2);
    const char* Khg = (const char*)Khi + bh * SEQ * (HD * 2);
    const char* Vhg = (const char*)Vhi + bh * SEQ * (HD * 2);

    // ---- load Q hi/lo (persistent smem) ----
    #pragma unroll
    for (int i = 0; i < 16; i++) {
        int idx = tid + i * 256;             // 4096 chunks
        int arr = idx >> 11;                 // 0:hi 1:lo
        int r   = (idx >> 4) & 127;
        int c   = (idx & 15) * 16;
        const char* sp = arr ? Qlg : Qhg;
        cp16(smb + arr * Q_ARR + r * AROWB + c, sp + (size_t)r * 256 + c);
    }
    asm volatile("cp.async.commit_group;" ::: "memory");

    auto loadKV = [&](int kt) {
        int s = kt & 1;
        #pragma unroll
        for (int i = 0; i < 8; i++) {
            int idx = tid + i * 256;         // 2048 chunks
            int arr = idx >> 10;             // 0:Khi 1:Vhi
            int r   = (idx >> 4) & 63;
            int c   = (idx & 15) * 16;
            const char* sp = arr ? Vhg : Khg;
            cp16(smb + KV_OFF + s * KV_STAGE + arr * KV_ARR + r * AROWB + c,
                 sp + (size_t)(kt * ATK + r) * 256 + c);
        }
        asm volatile("cp.async.commit_group;" ::: "memory");
    };

    loadKV(0);

    float oAcc[16][4];
    #pragma unroll
    for (int t2 = 0; t2 < 16; t2++)
        #pragma unroll
        for (int u = 0; u < 4; u++) oAcc[t2][u] = 0.f;
    float mA = -INFINITY, mB = -INFINITY, lA = 0.f, lB = 0.f;

    const int m0 = wid * 16;
    const int a_row  = lane & 15;
    const int a_halfB = (lane >> 4) * 16;
    const int b_row  = ((lane >> 4) << 3) + (lane & 7);
    const int b_halfB = ((lane >> 3) & 1) * 16;
    const float SCALE = 0.08838834764831845f;          // 1/sqrt(128)

    for (int kt = 0; kt < NKT; kt++) {
        if (kt + 1 < NKT) {
            loadKV(kt + 1);
            asm volatile("cp.async.wait_group 1;" ::: "memory");
        } else {
            asm volatile("cp.async.wait_group 0;" ::: "memory");
        }
        __syncthreads();

        const uint32_t kb   = smb + KV_OFF + (kt & 1) * KV_STAGE;
        const uint32_t KhiS = kb;
        const uint32_t VhiS = kb + KV_ARR;

        // ---- S = scale * (Qhi + Qlo) Khi^T ----
        float sAcc[8][4];
        #pragma unroll
        for (int ni = 0; ni < 8; ni++)
            #pragma unroll
            for (int u = 0; u < 4; u++) sAcc[ni][u] = 0.f;

        #pragma unroll
        for (int j = 0; j < 8; j++) {
            uint32_t ah[4], al[4];
            uint32_t aoff = (m0 + a_row) * AROWB + j * 32 + a_halfB;
            ldsm_x4(ah, smb + aoff);
            ldsm_x4(al, smb + Q_ARR + aoff);
            uint32_t bh_[4][4];
            #pragma unroll
            for (int nb = 0; nb < 4; nb++)
                ldsm_x4(bh_[nb], KhiS + (nb * 16 + b_row) * AROWB + j * 32 + b_halfB);
            #pragma unroll
            for (int ni = 0; ni < 8; ni++) {
                const uint32_t* Bh = &bh_[ni >> 1][(ni & 1) * 2];
                mma_f16(sAcc[ni], ah, Bh);
                mma_f16(sAcc[ni], al, Bh);
            }
        }

        // ---- online softmax ----
        float mxA = -INFINITY, mxB = -INFINITY;
        #pragma unroll
        for (int ni = 0; ni < 8; ni++) {
            #pragma unroll
            for (int u = 0; u < 4; u++) sAcc[ni][u] *= SCALE;
            mxA = fmaxf(mxA, fmaxf(sAcc[ni][0], sAcc[ni][1]));
            mxB = fmaxf(mxB, fmaxf(sAcc[ni][2], sAcc[ni][3]));
        }
        mxA = fmaxf(mxA, __shfl_xor_sync(0xffffffff, mxA, 1));
        mxA = fmaxf(mxA, __shfl_xor_sync(0xffffffff, mxA, 2));
        mxB = fmaxf(mxB, __shfl_xor_sync(0xffffffff, mxB, 1));
        mxB = fmaxf(mxB, __shfl_xor_sync(0xffffffff, mxB, 2));

        float mAn = fmaxf(mA, mxA), mBn = fmaxf(mB, mxB);
        float cA = __expf(mA - mAn), cB = __expf(mB - mBn);
        mA = mAn; mB = mBn;

        float sumA = 0.f, sumB = 0.f;
        #pragma unroll
        for (int ni = 0; ni < 8; ni++) {
            sAcc[ni][0] = __expf(sAcc[ni][0] - mA);
            sAcc[ni][1] = __expf(sAcc[ni][1] - mA);
            sAcc[ni][2] = __expf(sAcc[ni][2] - mB);
            sAcc[ni][3] = __expf(sAcc[ni][3] - mB);
            sumA += sAcc[ni][0] + sAcc[ni][1];
            sumB += sAcc[ni][2] + sAcc[ni][3];
        }
        sumA += __shfl_xor_sync(0xffffffff, sumA, 1);
        sumA += __shfl_xor_sync(0xffffffff, sumA, 2);
        sumB += __shfl_xor_sync(0xffffffff, sumB, 1);
        sumB += __shfl_xor_sync(0xffffffff, sumB, 2);
        lA = lA * cA + sumA;
        lB = lB * cB + sumB;

        #pragma unroll
        for (int t2 = 0; t2 < 16; t2++) {
            oAcc[t2][0] *= cA; oAcc[t2][1] *= cA;
            oAcc[t2][2] *= cB; oAcc[t2][3] *= cB;
        }

        // ---- pack P into hi/lo A-fragments (register-only) ----
        uint32_t phi[4][4], plo[4][4];
        #pragma unroll
        for (int j2 = 0; j2 < 4; j2++) {
            pack_hilo(sAcc[2*j2][0],   sAcc[2*j2][1],   phi[j2][0], plo[j2][0]);
            pack_hilo(sAcc[2*j2][2],   sAcc[2*j2][3],   phi[j2][1], plo[j2][1]);
            pack_hilo(sAcc[2*j2+1][0], sAcc[2*j2+1][1], phi[j2][2], plo[j2][2]);
            pack_hilo(sAcc[2*j2+1][2], sAcc[2*j2+1][3], phi[j2][3], plo[j2][3]);
        }

        // ---- O += (Phi + Plo) Vhi ----
        #pragma unroll
        for (int j2 = 0; j2 < 4; j2++) {
            int key0 = j2 * 16;
            #pragma unroll
            for (int nb = 0; nb < 8; nb++) {
                uint32_t vh[4];
                uint32_t voff = (key0 + (lane & 15)) * AROWB
                              + (nb * 16 + ((lane >> 4) << 3)) * 2;
                ldsm_x4_t(vh, VhiS + voff);
                mma_f16(oAcc[2*nb],   phi[j2], vh);
                mma_f16(oAcc[2*nb],   plo[j2], vh);
                mma_f16(oAcc[2*nb+1], phi[j2], vh + 2);
                mma_f16(oAcc[2*nb+1], plo[j2], vh + 2);
            }
        }
        __syncthreads();
    }

    // ---- epilogue: normalize + split to fp16 hi/lo, write AOhat [hi|lo] layout ----
    float invA = 1.0f / lA, invB = 1.0f / lB;
    int rA = qBase + m0 + (lane >> 2);
    int rB = rA + 8;
    __half* rowA = AOhat + (size_t)(b * SEQ + rA) * KT2 + h * HD;
    __half* rowB = AOhat + (size_t)(b * SEQ + rB) * KT2 + h * HD;
    #pragma unroll
    for (int t2 = 0; t2 < 16; t2++) {
        int cn = t2 * 8 + (lane & 3) * 2;
        float a0 = oAcc[t2][0] * invA, a1 = oAcc[t2][1] * invA;
        float b0 = oAcc[t2][2] * invB, b1 = oAcc[t2][3] * invB;
        uint32_t ahi, alo, bhi, blo;
        pack_hilo(a0, a1, ahi, alo);
        pack_hilo(b0, b1, bhi, blo);
        *(uint32_t*)(rowA + cn)           = ahi;
        *(uint32_t*)(rowA + D_MODEL + cn) = alo;
        *(uint32_t*)(rowB + cn)           = bhi;
        *(uint32_t*)(rowB + D_MODEL + cn) = blo;
    }
}

// ---------------- launch ----------------
extern "C" void kernel_launch(void* const* d_in, const int* in_sizes, int n_in,
                              void* d_out, int out_size)
{
    const float* x  = (const float*)d_in[0];
    const float* Wq = (const float*)d_in[1];
    const float* bq = (const float*)d_in[2];
    const float* Wk = (const float*)d_in[3];
    const float* bk = (const float*)d_in[4];
    const float* Wv = (const float*)d_in[5];
    const float* bv = (const float*)d_in[6];
    const float* Wo = (const float*)d_in[7];
    const float* bo = (const float*)d_in[8];
    float* out = (float*)d_out;

    float* scratch = nullptr;
    cudaGetSymbolAddress((void**)&scratch, g_scratch);
    const size_t NMe = (size_t)MROWS * D_MODEL;
    float* Qlin = scratch + 0 * NMe;
    float* Klin = scratch + 1 * NMe;
    float* Vlin = scratch + 2 * NMe;

    __half* hp = nullptr;
    cudaGetSymbolAddress((void**)&hp, g_half);
    const size_t XH = (size_t)MROWS * KT2;
    const size_t WH = (size_t)D_MODEL * KT2;
    __half* Xhat  = hp;
    __half* AOhat = hp + XH;
    __half* WqH   = hp + 2 * XH;
    __half* WkH   = WqH + WH;
    __half* WvH   = WkH + WH;
    __half* WoH   = WvH + WH;

    __half* ap = nullptr;
    cudaGetSymbolAddress((void**)&ap, g_attn);
    const size_t AH = (size_t)BHS * HD;
    __half* Qhi = ap + 0 * AH;
    __half* Qlo = ap + 1 * AH;
    __half* Khi = ap + 2 * AH;
    __half* Vhi = ap + 3 * AH;

    cudaFuncSetAttribute(gemm_mma_kernel, cudaFuncAttributeMaxDynamicSharedMemorySize,
                         GEMM_SMEM);
    cudaFuncSetAttribute(attn_mma_kernel, cudaFuncAttributeMaxDynamicSharedMemorySize,
                         ATTN_SMEM);

    // split operands to 2-term fp16
    split_kernel<<<(MROWS * D_MODEL) / 256, 256>>>(x,  Xhat, 0);
    split_kernel<<<(D_MODEL * D_MODEL) / 256, 256>>>(Wq, WqH, 1);
    split_kernel<<<(D_MODEL * D_MODEL) / 256, 256>>>(Wk, WkH, 1);
    split_kernel<<<(D_MODEL * D_MODEL) / 256, 256>>>(Wv, WvH, 1);
    split_kernel<<<(D_MODEL * D_MODEL) / 256, 256>>>(Wo, WoH, 1);

    dim3 ggrid(D_MODEL / BN, MROWS / BM);   // (16, 32)
    gemm_mma_kernel<<<ggrid, 256, GEMM_SMEM>>>(Xhat, WqH, bq, Qlin, D_MODEL);
    gemm_mma_kernel<<<ggrid, 256, GEMM_SMEM>>>(Xhat, WkH, bk, Klin, D_MODEL);
    gemm_mma_kernel<<<ggrid, 256, GEMM_SMEM>>>(Xhat, WvH, bv, Vlin, D_MODEL);

    int total = BATCH * NHEADS * SEQ * HD;
    rope_split_kernel<<<total / 256, 256>>>(Qlin, Klin, Vlin, Qhi, Qlo, Khi, Vhi);

    attn_mma_kernel<<<dim3(SEQ / ATQ, NHEADS, BATCH), 256, ATTN_SMEM>>>(
        Qhi, Qlo, Khi, Vhi, AOhat);

    gemm_mma_kernel<<<ggrid, 256, GEMM_SMEM>>>(AOhat, WoH, bo, out, D_MODEL);
}